// round 2
// baseline (speedup 1.0000x reference)
#include <cuda_runtime.h>
#include <cuda_bf16.h>
#include <math.h>

#define N_ANCH 6000
#define N_CLS  81
#define PAD    300
#define MASK_SZ (14*14*81)   // 15876
#define NMS_THRESH 0.5f
#define NMS_T 1024
#define NMS_K 6              // ceil(6000/1024)

// ---------------- scratch (device globals, no allocation) ----------------
__device__ float g_pbox[N_ANCH * 4];   // selected-class box per anchor (clipped)
__device__ float g_nscore[N_ANCH];     // max score over classes 1..C-1
__device__ int   g_idx[PAD];           // NMS selections
__device__ float g_valid[PAD];         // 1.0 / 0.0

// ---------------- kernel 1: per-anchor argmax + box decode ----------------
__global__ void k_decode(const float* __restrict__ meta,
                         const float* __restrict__ deltas,
                         const float* __restrict__ props,
                         const float* __restrict__ scores)
{
    int warp = (blockIdx.x * blockDim.x + threadIdx.x) >> 5;
    int lane = threadIdx.x & 31;
    if (warp >= N_ANCH) return;

    const float* srow = scores + (size_t)warp * N_CLS;
    float bv = -INFINITY; int bc = 0;
    float ms = -INFINITY;
    for (int c = lane; c < N_CLS; c += 32) {
        float v = srow[c];
        if (v > bv) { bv = v; bc = c; }     // first-occurrence per lane (ascending c)
        if (c >= 1) ms = fmaxf(ms, v);
    }
    // warp reduce: max value, smaller index on tie (matches jnp.argmax)
    #pragma unroll
    for (int off = 16; off; off >>= 1) {
        float ov  = __shfl_down_sync(0xffffffffu, bv, off);
        int   oc  = __shfl_down_sync(0xffffffffu, bc, off);
        float oms = __shfl_down_sync(0xffffffffu, ms, off);
        if (ov > bv || (ov == bv && oc < bc)) { bv = ov; bc = oc; }
        ms = fmaxf(ms, oms);
    }

    if (lane == 0) {
        float H = meta[0], W = meta[1], scale = meta[2];
        const float* p = props + (size_t)warp * 4;
        float x1 = p[0] / scale, y1 = p[1] / scale;
        float x2 = p[2] / scale, y2 = p[3] / scale;
        float w  = x2 - x1 + 1.0f, h = y2 - y1 + 1.0f;
        float cx = x1 + 0.5f * w, cy = y1 + 0.5f * h;

        const float* d = deltas + (size_t)warp * (4 * N_CLS) + bc * 4;
        float pcx = d[0] * w + cx;
        float pcy = d[1] * h + cy;
        float pw  = expf(d[2]) * w;
        float ph  = expf(d[3]) * h;

        float px1 = pcx - 0.5f * pw, py1 = pcy - 0.5f * ph;
        float px2 = pcx + 0.5f * pw, py2 = pcy + 0.5f * ph;
        // clip (jnp.clip(x, 0, W-1) == min(max(x,0), W-1))
        px1 = fminf(fmaxf(px1, 0.0f), W - 1.0f);
        py1 = fminf(fmaxf(py1, 0.0f), H - 1.0f);
        px2 = fminf(fmaxf(px2, 0.0f), W - 1.0f);
        py2 = fminf(fmaxf(py2, 0.0f), H - 1.0f);

        g_pbox[warp * 4 + 0] = px1;
        g_pbox[warp * 4 + 1] = py1;
        g_pbox[warp * 4 + 2] = px2;
        g_pbox[warp * 4 + 3] = py2;
        g_nscore[warp] = ms;
    }
}

// ---------------- kernel 2: greedy NMS, single persistent block ----------------
__global__ __launch_bounds__(NMS_T, 1)
void k_nms()
{
    const int tid  = threadIdx.x;
    const int lane = tid & 31;
    const int wid  = tid >> 5;

    __shared__ float s_val[32];
    __shared__ int   s_idx[32];
    __shared__ float s_box[5];   // x1,y1,x2,y2,area of selected

    // register-resident state: elements j = tid + k*1024
    float rx1[NMS_K], ry1[NMS_K], rx2[NMS_K], ry2[NMS_K], rar[NMS_K], rsc[NMS_K];
    #pragma unroll
    for (int k = 0; k < NMS_K; k++) {
        int j = tid + k * NMS_T;
        if (j < N_ANCH) {
            float4 b = *reinterpret_cast<const float4*>(&g_pbox[j * 4]);
            rx1[k] = b.x; ry1[k] = b.y; rx2[k] = b.z; ry2[k] = b.w;
            rar[k] = (b.z - b.x + 1.0f) * (b.w - b.y + 1.0f);
            rsc[k] = g_nscore[j];
        } else {
            rx1[k] = 0.f; ry1[k] = 0.f; rx2[k] = 0.f; ry2[k] = 0.f;
            rar[k] = 1.f; rsc[k] = -INFINITY;
        }
    }

    for (int iter = 0; iter < PAD; iter++) {
        // ---- local argmax (first-occurrence: strict >, indices ascend per thread)
        float bv = rsc[0]; int bi = tid;
        #pragma unroll
        for (int k = 1; k < NMS_K; k++) {
            int j = tid + k * NMS_T;
            if (j < N_ANCH && rsc[k] > bv) { bv = rsc[k]; bi = j; }
        }
        // warp reduce (tie -> smaller index)
        #pragma unroll
        for (int off = 16; off; off >>= 1) {
            float ov = __shfl_down_sync(0xffffffffu, bv, off);
            int   oi = __shfl_down_sync(0xffffffffu, bi, off);
            if (ov > bv || (ov == bv && oi < bi)) { bv = ov; bi = oi; }
        }
        if (lane == 0) { s_val[wid] = bv; s_idx[wid] = bi; }
        __syncthreads();

        // ---- every warp redundantly reduces the 32 partials (skips a barrier)
        float fv = s_val[lane];
        int   fi = s_idx[lane];
        #pragma unroll
        for (int off = 16; off; off >>= 1) {
            float ov = __shfl_down_sync(0xffffffffu, fv, off);
            int   oi = __shfl_down_sync(0xffffffffu, fi, off);
            if (ov > fv || (ov == fv && oi < fi)) { fv = ov; fi = oi; }
        }
        float winv = __shfl_sync(0xffffffffu, fv, 0);
        int   wini = __shfl_sync(0xffffffffu, fi, 0);

        if (tid == 0) {
            g_idx[iter]   = wini;
            g_valid[iter] = (winv > -INFINITY) ? 1.0f : 0.0f;
        }
        if (tid == (wini & (NMS_T - 1))) {
            int k = wini >> 10;
            s_box[0] = rx1[k]; s_box[1] = ry1[k];
            s_box[2] = rx2[k]; s_box[3] = ry2[k];
            s_box[4] = rar[k];
        }
        __syncthreads();

        // ---- suppression
        float bx1 = s_box[0], by1 = s_box[1], bx2 = s_box[2], by2 = s_box[3], ba = s_box[4];
        #pragma unroll
        for (int k = 0; k < NMS_K; k++) {
            int j = tid + k * NMS_T;
            if (j < N_ANCH && rsc[k] > -INFINITY) {
                float xx1 = fmaxf(bx1, rx1[k]);
                float yy1 = fmaxf(by1, ry1[k]);
                float xx2 = fminf(bx2, rx2[k]);
                float yy2 = fminf(by2, ry2[k]);
                float iw = fmaxf(xx2 - xx1 + 1.0f, 0.0f);
                float ih = fmaxf(yy2 - yy1 + 1.0f, 0.0f);
                float inter = iw * ih;
                float iou = inter / (ba + rar[k] - inter);
                if (iou > NMS_THRESH || j == wini) rsc[k] = -INFINITY;
            }
        }
        // next iteration's first barrier orders s_box reads vs. rewrites
    }
}

// ---------------- kernel 3: gather outputs ----------------
// out layout: [300*4 boxes][300*81 scores][300*15876 masks]
#define OFF_SC  (PAD * 4)
#define OFF_MK  (OFF_SC + PAD * N_CLS)
#define TOTAL_OUT (OFF_MK + PAD * MASK_SZ)

__global__ void k_gather(const float* __restrict__ scores,
                         const float* __restrict__ masks,
                         float* __restrict__ out)
{
    int e = blockIdx.x * blockDim.x + threadIdx.x;
    if (e >= TOTAL_OUT) return;

    if (e < OFF_SC) {
        int k = e >> 2, c = e & 3;
        out[e] = g_pbox[g_idx[k] * 4 + c] * g_valid[k];
    } else if (e < OFF_MK) {
        int r = e - OFF_SC;
        int k = r / N_CLS, c = r - k * N_CLS;
        out[e] = scores[(size_t)g_idx[k] * N_CLS + c] * g_valid[k];
    } else {
        int r = e - OFF_MK;
        int k = r / MASK_SZ, m = r - k * MASK_SZ;
        out[e] = masks[(size_t)g_idx[k] * MASK_SZ + m] * g_valid[k];
    }
}

// ---------------- launch ----------------
extern "C" void kernel_launch(void* const* d_in, const int* in_sizes, int n_in,
                              void* d_out, int out_size)
{
    const float* meta   = (const float*)d_in[0];
    const float* deltas = (const float*)d_in[1];
    const float* props  = (const float*)d_in[2];
    const float* scores = (const float*)d_in[3];
    const float* masks  = (const float*)d_in[4];
    float* out = (float*)d_out;

    // 1 warp per anchor, 4 warps per block
    k_decode<<<(N_ANCH + 3) / 4, 128>>>(meta, deltas, props, scores);
    // single-block sequential NMS
    k_nms<<<1, NMS_T>>>();
    // gather all outputs
    k_gather<<<(TOTAL_OUT + 255) / 256, 256>>>(scores, masks, out);
}

// round 3
// speedup vs baseline: 4.2226x; 4.2226x over previous
#include <cuda_runtime.h>
#include <cuda_bf16.h>
#include <math.h>

#define N_ANCH 6000
#define N_CLS  81
#define PAD    300
#define MASK_SZ (14*14*81)   // 15876
#define NMS_THRESH 0.5f
#define T      1024
#define NSORT  8192
#define CH     512
#define MAT_STRIDE 516       // words; padded to break LDS bank conflicts

// ---------------- scratch (device globals, no allocation) ----------------
__device__ float4 g_pbox[N_ANCH];     // selected-class box per anchor (clipped)
__device__ float  g_nscore[N_ANCH];   // max score over classes 1..C-1
__device__ int    g_idx[PAD];         // NMS selections
__device__ float  g_valid[PAD];       // 1.0 / 0.0

// ---------------- kernel 1: per-anchor argmax + box decode ----------------
__global__ void k_decode(const float* __restrict__ meta,
                         const float* __restrict__ deltas,
                         const float* __restrict__ props,
                         const float* __restrict__ scores)
{
    int warp = (blockIdx.x * blockDim.x + threadIdx.x) >> 5;
    int lane = threadIdx.x & 31;
    if (warp >= N_ANCH) return;

    const float* srow = scores + (size_t)warp * N_CLS;
    float bv = -INFINITY; int bc = 0;
    float ms = -INFINITY;
    for (int c = lane; c < N_CLS; c += 32) {
        float v = srow[c];
        if (v > bv) { bv = v; bc = c; }     // first-occurrence per lane (ascending c)
        if (c >= 1) ms = fmaxf(ms, v);
    }
    #pragma unroll
    for (int off = 16; off; off >>= 1) {
        float ov  = __shfl_down_sync(0xffffffffu, bv, off);
        int   oc  = __shfl_down_sync(0xffffffffu, bc, off);
        float oms = __shfl_down_sync(0xffffffffu, ms, off);
        if (ov > bv || (ov == bv && oc < bc)) { bv = ov; bc = oc; }
        ms = fmaxf(ms, oms);
    }

    if (lane == 0) {
        float H = meta[0], W = meta[1], scale = meta[2];
        const float* p = props + (size_t)warp * 4;
        float x1 = p[0] / scale, y1 = p[1] / scale;
        float x2 = p[2] / scale, y2 = p[3] / scale;
        float w  = x2 - x1 + 1.0f, h = y2 - y1 + 1.0f;
        float cx = x1 + 0.5f * w, cy = y1 + 0.5f * h;

        const float* d = deltas + (size_t)warp * (4 * N_CLS) + bc * 4;
        float pcx = d[0] * w + cx;
        float pcy = d[1] * h + cy;
        float pw  = expf(d[2]) * w;
        float ph  = expf(d[3]) * h;

        float px1 = pcx - 0.5f * pw, py1 = pcy - 0.5f * ph;
        float px2 = pcx + 0.5f * pw, py2 = pcy + 0.5f * ph;
        px1 = fminf(fmaxf(px1, 0.0f), W - 1.0f);
        py1 = fminf(fmaxf(py1, 0.0f), H - 1.0f);
        px2 = fminf(fmaxf(px2, 0.0f), W - 1.0f);
        py2 = fminf(fmaxf(py2, 0.0f), H - 1.0f);

        g_pbox[warp] = make_float4(px1, py1, px2, py2);
        g_nscore[warp] = ms;
    }
}

// IoU suppression test — exact expression order of the reference (adds commutative)
__device__ __forceinline__ bool iou_sup(float4 a, float aa, float4 b, float ba)
{
    float xx1 = fmaxf(a.x, b.x);
    float yy1 = fmaxf(a.y, b.y);
    float xx2 = fminf(a.z, b.z);
    float yy2 = fminf(a.w, b.w);
    float iw = fmaxf(xx2 - xx1 + 1.0f, 0.0f);
    float ih = fmaxf(yy2 - yy1 + 1.0f, 0.0f);
    float inter = iw * ih;
    return inter / (aa + ba - inter) > NMS_THRESH;
}

// ---------------- kernel 2: sorted-greedy NMS ----------------
// smem layout (bytes):
//   keys   u64[8192]          @ 0       (65536)
//   sidx   u16[6000]          @ 65536   (12032 padded)
//   cbox   float4[CH]         @ 77568   (8192)
//   carea  float[CH]          @ 85760   (2048)
//   sprev  u32[CH]            @ 87808   (2048)
//   mat    u32[16*MAT_STRIDE] @ 89856   (33024)
//   kbox   float4[PAD]        @ 122880  (4800)
//   karea  float[PAD]         @ 127680  (1200)
//   s_kept int                @ 128880
#define SMEM_TOTAL 128896

__global__ __launch_bounds__(T, 1) void k_nms()
{
    extern __shared__ char sm[];
    unsigned long long* keys = (unsigned long long*)(sm);
    unsigned short* sidx     = (unsigned short*)(sm + 65536);
    float4*   cbox  = (float4*)(sm + 77568);
    float*    carea = (float*)(sm + 85760);
    unsigned* sprev = (unsigned*)(sm + 87808);
    unsigned* mat   = (unsigned*)(sm + 89856);
    float4*   kbox  = (float4*)(sm + 122880);
    float*    karea = (float*)(sm + 127680);
    int*      s_kept = (int*)(sm + 128880);

    const int tid = threadIdx.x;
    const int lane = tid & 31;

    // ---- build sort keys: descending score, ascending index on ties ----
    for (int i = tid; i < NSORT; i += T)
        keys[i] = (i < N_ANCH)
            ? ((unsigned long long)__float_as_uint(g_nscore[i]) << 32) | (unsigned)(0xFFFFFFFFu - (unsigned)i)
            : 0ull;
    __syncthreads();

    // ---- bitonic sort, descending ----
    for (int k = 2; k <= NSORT; k <<= 1) {
        for (int j = k >> 1; j > 0; j >>= 1) {
            #pragma unroll
            for (int s = 0; s < NSORT / T; s++) {
                int i = tid + s * T;
                int ixj = i ^ j;
                if (ixj > i) {
                    unsigned long long a = keys[i], b = keys[ixj];
                    bool up = ((i & k) == 0);
                    if (up ? (a < b) : (a > b)) { keys[i] = b; keys[ixj] = a; }
                }
            }
            __syncthreads();
        }
    }

    // ---- extract sorted original indices ----
    for (int r = tid; r < N_ANCH; r += T)
        sidx[r] = (unsigned short)(~(unsigned)keys[r]);
    if (tid == 0) *s_kept = 0;
    __syncthreads();

    int kept = 0;
    for (int base = 0; base < N_ANCH && kept < PAD; base += CH) {
        int cn = min(CH, N_ANCH - base);

        // load candidate boxes + areas
        for (int c = tid; c < cn; c += T) {
            int idx = sidx[base + c];
            float4 b = g_pbox[idx];
            cbox[c] = b;
            carea[c] = (b.z - b.x + 1.0f) * (b.w - b.y + 1.0f);
        }
        __syncthreads();

        // suppressed-by-previous-chunk-keeps flags
        if (base == 0) {
            for (int c = tid; c < cn; c += T) sprev[c] = 0;
        } else {
            for (int c = tid; c < cn; c += T) {
                float4 b = cbox[c]; float ba = carea[c];
                unsigned f = 0;
                for (int q = 0; q < kept; q++)
                    if (iou_sup(kbox[q], karea[q], b, ba)) { f = 1; break; }
                sprev[c] = f;
            }
        }

        // within-chunk suppression bitmatrix: mat[w][i] = bits of j in [32w,32w+32)∩[0,i)
        for (int iw = tid; iw < CH * 16; iw += T) {
            int i = iw & (CH - 1);
            int w = iw >> 9;
            int j0 = w << 5;
            if (i < cn && j0 < i) {
                float4 bi = cbox[i]; float ai = carea[i];
                int jmax = min(i, j0 + 32);
                unsigned word = 0;
                for (int j = j0; j < jmax; j++)
                    if (iou_sup(cbox[j], carea[j], bi, ai)) word |= 1u << (j - j0);
                mat[w * MAT_STRIDE + i] = word;
            }
        }
        __syncthreads();

        // serial resolution by warp 0 (keep mask in registers, prefetched rows)
        if (tid < 32) {
            unsigned km = 0;   // lane l holds kept-bit word for j in [32l, 32l+32)
            int kp = kept;
            unsigned row = (lane < 16 && cn > 0) ? mat[lane * MAT_STRIDE] : 0u;
            for (int i = 0; i < cn && kp < PAD; i++) {
                unsigned nrow = (lane < 16 && i + 1 < cn) ? mat[lane * MAT_STRIDE + i + 1] : 0u;
                unsigned sp = sprev[i];
                bool clash = __any_sync(0xffffffffu, (row & km) != 0u) || (sp != 0u);
                if (!clash) {
                    if (lane == 0) {
                        g_idx[kp]   = (int)sidx[base + i];
                        g_valid[kp] = 1.0f;
                        kbox[kp]    = cbox[i];
                        karea[kp]   = carea[i];
                    }
                    if (lane == (i >> 5)) km |= 1u << (i & 31);
                    kp++;
                }
                row = nrow;
            }
            if (lane == 0) *s_kept = kp;
        }
        __syncthreads();
        kept = *s_kept;
    }

    // tail fill (exhausted candidates with < PAD keeps)
    for (int r = kept + tid; r < PAD; r += T) { g_idx[r] = 0; g_valid[r] = 0.0f; }
}

// ---------------- kernel 3: gather outputs ----------------
// out layout: [300*4 boxes][300*81 scores][300*15876 masks]
#define OFF_SC  (PAD * 4)
#define OFF_MK  (OFF_SC + PAD * N_CLS)

__global__ void k_gather_small(const float* __restrict__ scores,
                               float* __restrict__ out)
{
    int e = blockIdx.x * blockDim.x + threadIdx.x;
    if (e >= OFF_MK) return;
    if (e < OFF_SC) {
        int k = e >> 2, c = e & 3;
        const float* bp = (const float*)&g_pbox[g_idx[k]];
        out[e] = bp[c] * g_valid[k];
    } else {
        int r = e - OFF_SC;
        int k = r / N_CLS, c = r - k * N_CLS;
        out[e] = scores[(size_t)g_idx[k] * N_CLS + c] * g_valid[k];
    }
}

__global__ void k_gather_masks(const float* __restrict__ masks,
                               float* __restrict__ out)
{
    const int per = MASK_SZ / 4;  // 3969 float4 per detection
    int e = blockIdx.x * blockDim.x + threadIdx.x;
    if (e >= PAD * per) return;
    int k = e / per, m = e - k * per;
    const float4* src = (const float4*)(masks + (size_t)g_idx[k] * MASK_SZ);
    float4 v = src[m];
    float s = g_valid[k];
    v.x *= s; v.y *= s; v.z *= s; v.w *= s;
    ((float4*)(out + OFF_MK))[e] = v;
}

// ---------------- launch ----------------
extern "C" void kernel_launch(void* const* d_in, const int* in_sizes, int n_in,
                              void* d_out, int out_size)
{
    const float* meta   = (const float*)d_in[0];
    const float* deltas = (const float*)d_in[1];
    const float* props  = (const float*)d_in[2];
    const float* scores = (const float*)d_in[3];
    const float* masks  = (const float*)d_in[4];
    float* out = (float*)d_out;

    static bool attr_done = false;
    if (!attr_done) {
        cudaFuncSetAttribute(k_nms, cudaFuncAttributeMaxDynamicSharedMemorySize, SMEM_TOTAL);
        attr_done = true;
    }

    k_decode<<<(N_ANCH + 3) / 4, 128>>>(meta, deltas, props, scores);
    k_nms<<<1, T, SMEM_TOTAL>>>();
    k_gather_small<<<(OFF_MK + 255) / 256, 256>>>(scores, out);
    k_gather_masks<<<(PAD * (MASK_SZ / 4) + 255) / 256, 256>>>(masks, out);
}

// round 4
// speedup vs baseline: 5.6794x; 1.3450x over previous
#include <cuda_runtime.h>
#include <cuda_bf16.h>
#include <math.h>

#define N_ANCH 6000
#define N_CLS  81
#define PAD    300
#define MASK_SZ (14*14*81)   // 15876
#define NMS_THRESH 0.5f
#define T      1024
#define TARGET 1024u
#define NSEL   4096
#define CH     512
#define MAT_STRIDE 516

// ---- dynamic smem layout (bytes) ----
// region A (phase-aliased):
//   selection: u32 hist[32768]                 @0      (131072)
//   nms:  cbox f4[512]@0, carea f32[512]@8192, sprev u32[512]@10240,
//         mat u32[16*516]@12288 (33024)
#define OFF_KEYS  131072   // u64[4096]  (32768)
#define OFF_S1    163840   // u32[1024]  (4096)
#define OFF_KBOX  167936   // float4[300] (4800)
#define OFF_KAREA 172736   // f32[300]   (1200)
#define OFF_SCAL  173936   // scalars
#define SMEM_TOTAL 174080

// ---------------- scratch (device globals, no allocation) ----------------
__device__ float4 g_pbox[N_ANCH];
__device__ float  g_nscore[N_ANCH];
__device__ int    g_idx[PAD];
__device__ float  g_valid[PAD];

// ---------------- kernel 1: per-anchor argmax + box decode ----------------
__global__ void k_decode(const float* __restrict__ meta,
                         const float* __restrict__ deltas,
                         const float* __restrict__ props,
                         const float* __restrict__ scores)
{
    int warp = (blockIdx.x * blockDim.x + threadIdx.x) >> 5;
    int lane = threadIdx.x & 31;
    if (warp >= N_ANCH) return;

    const float* srow = scores + (size_t)warp * N_CLS;
    float bv = -INFINITY; int bc = 0;
    float ms = -INFINITY;
    for (int c = lane; c < N_CLS; c += 32) {
        float v = srow[c];
        if (v > bv) { bv = v; bc = c; }
        if (c >= 1) ms = fmaxf(ms, v);
    }
    #pragma unroll
    for (int off = 16; off; off >>= 1) {
        float ov  = __shfl_down_sync(0xffffffffu, bv, off);
        int   oc  = __shfl_down_sync(0xffffffffu, bc, off);
        float oms = __shfl_down_sync(0xffffffffu, ms, off);
        if (ov > bv || (ov == bv && oc < bc)) { bv = ov; bc = oc; }
        ms = fmaxf(ms, oms);
    }

    if (lane == 0) {
        float H = meta[0], W = meta[1], scale = meta[2];
        const float* p = props + (size_t)warp * 4;
        float x1 = p[0] / scale, y1 = p[1] / scale;
        float x2 = p[2] / scale, y2 = p[3] / scale;
        float w  = x2 - x1 + 1.0f, h = y2 - y1 + 1.0f;
        float cx = x1 + 0.5f * w, cy = y1 + 0.5f * h;

        const float* d = deltas + (size_t)warp * (4 * N_CLS) + bc * 4;
        float pcx = d[0] * w + cx;
        float pcy = d[1] * h + cy;
        float pw  = expf(d[2]) * w;
        float ph  = expf(d[3]) * h;

        float px1 = pcx - 0.5f * pw, py1 = pcy - 0.5f * ph;
        float px2 = pcx + 0.5f * pw, py2 = pcy + 0.5f * ph;
        px1 = fminf(fmaxf(px1, 0.0f), W - 1.0f);
        py1 = fminf(fmaxf(py1, 0.0f), H - 1.0f);
        px2 = fminf(fmaxf(px2, 0.0f), W - 1.0f);
        py2 = fminf(fmaxf(py2, 0.0f), H - 1.0f);

        g_pbox[warp] = make_float4(px1, py1, px2, py2);
        g_nscore[warp] = ms;
    }
}

__device__ __forceinline__ bool iou_sup(float4 a, float aa, float4 b, float ba)
{
    float xx1 = fmaxf(a.x, b.x);
    float yy1 = fmaxf(a.y, b.y);
    float xx2 = fminf(a.z, b.z);
    float yy2 = fminf(a.w, b.w);
    float iw = fmaxf(xx2 - xx1 + 1.0f, 0.0f);
    float ih = fmaxf(yy2 - yy1 + 1.0f, 0.0f);
    float inter = iw * ih;
    return inter / (aa + ba - inter) > NMS_THRESH;
}

// warp-0 hierarchical suffix search over 65536-bucket histogram.
// finds threshold bucket b: count(bucket > b) < target <= count(bucket >= b)
// writes *s_b = b, *s_above = count strictly above b; *s_all = 1 if total < target.
__device__ __forceinline__ void warp_select(const unsigned* hist, const unsigned* s1,
                                            unsigned target,
                                            volatile unsigned* s_b,
                                            volatile unsigned* s_above,
                                            volatile int* s_all)
{
    int lane = threadIdx.x;   // caller guarantees tid < 32

    // L1: 32 groups of 32 s1-entries (each s1 entry = 64 buckets)
    unsigned s2 = 0;
    #pragma unroll 8
    for (int q = 0; q < 32; q++) s2 += s1[lane * 32 + q];
    unsigned incl = s2;
    #pragma unroll
    for (int off = 1; off < 32; off <<= 1) {
        unsigned v = __shfl_down_sync(0xffffffffu, incl, off);
        if (lane + off < 32) incl += v;
    }
    unsigned total = __shfl_sync(0xffffffffu, incl, 0);
    if (total < target) { if (lane == 0) *s_all = 1; return; }
    if (lane == 0) *s_all = 0;

    unsigned bal = __ballot_sync(0xffffffffu, incl >= target);
    int L1 = 31 - __clz(bal);
    unsigned carry1 = __shfl_sync(0xffffffffu, incl, (L1 + 1) & 31);
    if (L1 == 31) carry1 = 0;

    // L2: 32 s1 entries inside group L1
    incl = s1[L1 * 32 + lane];
    #pragma unroll
    for (int off = 1; off < 32; off <<= 1) {
        unsigned v = __shfl_down_sync(0xffffffffu, incl, off);
        if (lane + off < 32) incl += v;
    }
    bal = __ballot_sync(0xffffffffu, carry1 + incl >= target);
    int L2 = 31 - __clz(bal);
    unsigned carry2 = __shfl_sync(0xffffffffu, incl, (L2 + 1) & 31);
    if (L2 == 31) carry2 = 0;
    carry2 += carry1;

    // L3: 64 buckets of s1-entry (L1*32+L2): lane holds one u32 word = 2 buckets
    int bbase = (L1 * 32 + L2) * 64;
    unsigned w = hist[(bbase >> 1) + lane];
    unsigned lowc = w & 0xFFFFu, highc = w >> 16;
    incl = lowc + highc;
    #pragma unroll
    for (int off = 1; off < 32; off <<= 1) {
        unsigned v = __shfl_down_sync(0xffffffffu, incl, off);
        if (lane + off < 32) incl += v;
    }
    bal = __ballot_sync(0xffffffffu, carry2 + incl >= target);
    int L3 = 31 - __clz(bal);
    unsigned carryn = __shfl_sync(0xffffffffu, incl, (L3 + 1) & 31);
    if (L3 == 31) carryn = 0;
    carryn += carry2;                     // strictly above the pair at L3

    if (lane == L3) {
        unsigned b, ab;
        if (carryn + highc >= target) { b = (unsigned)(bbase + 2 * L3 + 1); ab = carryn; }
        else                          { b = (unsigned)(bbase + 2 * L3);     ab = carryn + highc; }
        *s_b = b; *s_above = ab;
    }
}

// ---------------- kernel 2: radix-select + sorted-greedy NMS ----------------
__global__ __launch_bounds__(T, 1) void k_nms()
{
    extern __shared__ char sm[];
    unsigned*           hist  = (unsigned*)(sm);
    float4*             cbox  = (float4*)(sm);
    float*              carea = (float*)(sm + 8192);
    unsigned*           sprev = (unsigned*)(sm + 10240);
    unsigned*           mat   = (unsigned*)(sm + 12288);
    unsigned long long* keys  = (unsigned long long*)(sm + OFF_KEYS);
    unsigned*           s1    = (unsigned*)(sm + OFF_S1);
    float4*             kbox  = (float4*)(sm + OFF_KBOX);
    float*              karea = (float*)(sm + OFF_KAREA);
    volatile unsigned*  s_cnt   = (volatile unsigned*)(sm + OFF_SCAL);
    volatile int*       s_kept  = (volatile int*)(sm + OFF_SCAL + 4);
    volatile unsigned*  s_b     = (volatile unsigned*)(sm + OFF_SCAL + 8);
    volatile unsigned*  s_above = (volatile unsigned*)(sm + OFF_SCAL + 12);
    volatile int*       s_all   = (volatile int*)(sm + OFF_SCAL + 16);

    const int tid = threadIdx.x;
    const int lane = tid & 31;

    if (tid == 0) *s_kept = 0;
    int kept = 0;
    unsigned hi = 0xFFFFFFFFu;   // inclusive upper bound on score bits

    while (kept < PAD) {
        // ===================== selection: pass 1 (bits >> 16) =====================
        for (int i = tid; i < 32768; i += T) hist[i] = 0;
        __syncthreads();
        for (int i = tid; i < N_ANCH; i += T) {
            unsigned bits = __float_as_uint(g_nscore[i]);
            if (bits <= hi) {
                unsigned b = bits >> 16;
                atomicAdd(&hist[b >> 1], 1u << ((b & 1) * 16));
            }
        }
        __syncthreads();
        {   // s1[t] = count in buckets [t*64, t*64+64)
            int t = tid;
            unsigned s = 0;
            #pragma unroll 8
            for (int q = 0; q < 32; q++) { unsigned w = hist[t * 32 + q]; s += (w & 0xFFFFu) + (w >> 16); }
            s1[t] = s;
        }
        __syncthreads();
        if (tid < 32) warp_select(hist, s1, TARGET, s_b, s_above, s_all);
        __syncthreads();

        unsigned lo;
        if (*s_all) {
            lo = 0u;   // fewer than TARGET remain: take everything <= hi
        } else {
            unsigned b1  = *s_b;
            unsigned chi = *s_above;
            // ===================== selection: pass 2 (bits & 0xFFFF within b1) ===
            __syncthreads();
            for (int i = tid; i < 32768; i += T) hist[i] = 0;
            __syncthreads();
            for (int i = tid; i < N_ANCH; i += T) {
                unsigned bits = __float_as_uint(g_nscore[i]);
                if (bits <= hi && (bits >> 16) == b1) {
                    unsigned b = bits & 0xFFFFu;
                    atomicAdd(&hist[b >> 1], 1u << ((b & 1) * 16));
                }
            }
            __syncthreads();
            {
                int t = tid;
                unsigned s = 0;
                #pragma unroll 8
                for (int q = 0; q < 32; q++) { unsigned w = hist[t * 32 + q]; s += (w & 0xFFFFu) + (w >> 16); }
                s1[t] = s;
            }
            __syncthreads();
            if (tid < 32) warp_select(hist, s1, TARGET - chi, s_b, s_above, s_all);
            __syncthreads();
            lo = (*s_all) ? (b1 << 16) : ((b1 << 16) | *s_b);
        }
        __syncthreads();

        // ===================== collect candidates in [lo, hi] =====================
        if (tid == 0) *s_cnt = 0;
        __syncthreads();
        for (int i = tid; i < N_ANCH; i += T) {
            unsigned bits = __float_as_uint(g_nscore[i]);
            if (bits >= lo && bits <= hi) {
                unsigned p = atomicAdd((unsigned*)s_cnt, 1u);
                if (p < NSEL)
                    keys[p] = ((unsigned long long)bits << 32) | (0xFFFFFFFFu - (unsigned)i);
            }
        }
        __syncthreads();
        int S = min((int)*s_cnt, NSEL);
        int nsort = (S <= 2048) ? 2048 : NSEL;
        for (int i = tid; i < nsort; i += T) if (i >= S) keys[i] = 0ull;
        __syncthreads();

        if (S > 0) {
            // ===================== bitonic sort (descending) ======================
            for (int k = 2; k <= nsort; k <<= 1) {
                for (int j = k >> 1; j > 0; j >>= 1) {
                    for (int i = tid; i < nsort; i += T) {
                        int ixj = i ^ j;
                        if (ixj > i) {
                            unsigned long long a = keys[i], b = keys[ixj];
                            bool up = ((i & k) == 0);
                            if (up ? (a < b) : (a > b)) { keys[i] = b; keys[ixj] = a; }
                        }
                    }
                    __syncthreads();
                }
            }

            // ===================== chunked NMS over sorted batch ==================
            for (int base = 0; base < S && kept < PAD; base += CH) {
                int cn = min(CH, S - base);

                for (int c = tid; c < cn; c += T) {
                    unsigned idx = 0xFFFFFFFFu - (unsigned)keys[base + c];
                    float4 b = g_pbox[idx];
                    cbox[c] = b;
                    carea[c] = (b.z - b.x + 1.0f) * (b.w - b.y + 1.0f);
                }
                __syncthreads();

                if (kept == 0) {
                    for (int c = tid; c < cn; c += T) sprev[c] = 0;
                } else {
                    for (int c = tid; c < cn; c += T) {
                        float4 b = cbox[c]; float ba = carea[c];
                        unsigned f = 0;
                        for (int q = 0; q < kept; q++)
                            if (iou_sup(kbox[q], karea[q], b, ba)) { f = 1; break; }
                        sprev[c] = f;
                    }
                }

                for (int iw = tid; iw < CH * 16; iw += T) {
                    int i = iw & (CH - 1);
                    int w = iw >> 9;
                    int j0 = w << 5;
                    if (i < cn && j0 < i) {
                        float4 bi = cbox[i]; float ai = carea[i];
                        int jmax = min(i, j0 + 32);
                        unsigned word = 0;
                        for (int j = j0; j < jmax; j++)
                            if (iou_sup(cbox[j], carea[j], bi, ai)) word |= 1u << (j - j0);
                        mat[w * MAT_STRIDE + i] = word;
                    }
                }
                __syncthreads();

                if (tid < 32) {
                    unsigned km = 0;
                    int kp = kept;
                    unsigned row = (lane < 16 && cn > 0) ? mat[lane * MAT_STRIDE] : 0u;
                    for (int i = 0; i < cn && kp < PAD; i++) {
                        unsigned nrow = (lane < 16 && i + 1 < cn) ? mat[lane * MAT_STRIDE + i + 1] : 0u;
                        unsigned sp = sprev[i];
                        bool clash = __any_sync(0xffffffffu, (row & km) != 0u) || (sp != 0u);
                        if (!clash) {
                            if (lane == 0) {
                                g_idx[kp]   = (int)(0xFFFFFFFFu - (unsigned)keys[base + i]);
                                g_valid[kp] = 1.0f;
                                kbox[kp]    = cbox[i];
                                karea[kp]   = carea[i];
                            }
                            if (lane == (i >> 5)) km |= 1u << (i & 31);
                            kp++;
                        }
                        row = nrow;
                    }
                    if (lane == 0) *s_kept = kp;
                }
                __syncthreads();
                kept = *s_kept;
            }
        }

        if (lo == 0u) break;      // processed every remaining candidate
        hi = lo - 1u;
        __syncthreads();
    }

    for (int r = kept + tid; r < PAD; r += T) { g_idx[r] = 0; g_valid[r] = 0.0f; }
}

// ---------------- kernel 3: gather outputs ----------------
#define OFF_SC  (PAD * 4)
#define OFF_MK  (OFF_SC + PAD * N_CLS)

__global__ void k_gather_small(const float* __restrict__ scores,
                               float* __restrict__ out)
{
    int e = blockIdx.x * blockDim.x + threadIdx.x;
    if (e >= OFF_MK) return;
    if (e < OFF_SC) {
        int k = e >> 2, c = e & 3;
        const float* bp = (const float*)&g_pbox[g_idx[k]];
        out[e] = bp[c] * g_valid[k];
    } else {
        int r = e - OFF_SC;
        int k = r / N_CLS, c = r - k * N_CLS;
        out[e] = scores[(size_t)g_idx[k] * N_CLS + c] * g_valid[k];
    }
}

__global__ void k_gather_masks(const float* __restrict__ masks,
                               float* __restrict__ out)
{
    const int per = MASK_SZ / 4;           // 3969 float4 per detection
    const int total = PAD * per;
    int base = (blockIdx.x * blockDim.x + threadIdx.x) * 4;
    float4* dst = (float4*)(out + OFF_MK);
    #pragma unroll
    for (int u = 0; u < 4; u++) {
        int e = base + u;
        if (e < total) {
            int k = e / per, m = e - k * per;
            const float4* src = (const float4*)(masks + (size_t)g_idx[k] * MASK_SZ);
            float4 v = __ldg(&src[m]);
            float s = g_valid[k];
            v.x *= s; v.y *= s; v.z *= s; v.w *= s;
            dst[e] = v;
        }
    }
}

// ---------------- launch ----------------
extern "C" void kernel_launch(void* const* d_in, const int* in_sizes, int n_in,
                              void* d_out, int out_size)
{
    const float* meta   = (const float*)d_in[0];
    const float* deltas = (const float*)d_in[1];
    const float* props  = (const float*)d_in[2];
    const float* scores = (const float*)d_in[3];
    const float* masks  = (const float*)d_in[4];
    float* out = (float*)d_out;

    static bool attr_done = false;
    if (!attr_done) {
        cudaFuncSetAttribute(k_nms, cudaFuncAttributeMaxDynamicSharedMemorySize, SMEM_TOTAL);
        attr_done = true;
    }

    k_decode<<<(N_ANCH + 3) / 4, 128>>>(meta, deltas, props, scores);
    k_nms<<<1, T, SMEM_TOTAL>>>();
    k_gather_small<<<(OFF_MK + 255) / 256, 256>>>(scores, out);
    {
        int thr = (PAD * (MASK_SZ / 4) + 3) / 4;
        k_gather_masks<<<(thr + 255) / 256, 256>>>(masks, out);
    }
}

// round 5
// speedup vs baseline: 5.8976x; 1.0384x over previous
#include <cuda_runtime.h>
#include <cuda_bf16.h>
#include <math.h>

#define N_ANCH 6000
#define N_CLS  81
#define PAD    300
#define MASK_SZ (14*14*81)   // 15876
#define NMS_THRESH 0.5f
#define T      1024
#define TARGET 512u
#define KEYCAP 8192
#define CH     512
#define MAT_STRIDE 516

// ---- dynamic smem layout (bytes), shared by k_select / k_resolve ----
// region A (phase-aliased with hist):
//   cbox f4[512]@0 (8192) | carea f32[512]@8192 (2048) | sprev u32[512]@10240 (2048)
//   cidx u32[512]@12288 (2048) | mat u32[16*516]@14336 (33024)
//   hist u32[32768]@0 (131072)   -- select phases only
#define OFF_KEYS  131072   // u64[8192]  (65536) -> 196608
#define OFF_S1    196608   // u32[1024]  (4096)  -> 200704
#define OFF_KBOX  200704   // float4[300](4800)  -> 205504
#define OFF_KAREA 205504   // f32[300]   (1200)  -> 206704
#define OFF_SCAL  206704
#define SMEM_TOTAL 206848

// ---------------- scratch (device globals, no allocation) ----------------
__device__ float4 g_pbox[N_ANCH];
__device__ float  g_nscore[N_ANCH];
__device__ unsigned long long g_skeys[KEYCAP];
__device__ int      g_S;
__device__ unsigned g_lo;
__device__ unsigned g_mat[16 * 512];
__device__ int    g_idx[PAD];
__device__ float  g_valid[PAD];

// ---------------- kernel 1: per-anchor argmax + box decode ----------------
__global__ void k_decode(const float* __restrict__ meta,
                         const float* __restrict__ deltas,
                         const float* __restrict__ props,
                         const float* __restrict__ scores)
{
    int warp = (blockIdx.x * blockDim.x + threadIdx.x) >> 5;
    int lane = threadIdx.x & 31;
    if (warp >= N_ANCH) return;

    const float* srow = scores + (size_t)warp * N_CLS;
    float bv = -INFINITY; int bc = 0;
    float ms = -INFINITY;
    for (int c = lane; c < N_CLS; c += 32) {
        float v = srow[c];
        if (v > bv) { bv = v; bc = c; }
        if (c >= 1) ms = fmaxf(ms, v);
    }
    #pragma unroll
    for (int off = 16; off; off >>= 1) {
        float ov  = __shfl_down_sync(0xffffffffu, bv, off);
        int   oc  = __shfl_down_sync(0xffffffffu, bc, off);
        float oms = __shfl_down_sync(0xffffffffu, ms, off);
        if (ov > bv || (ov == bv && oc < bc)) { bv = ov; bc = oc; }
        ms = fmaxf(ms, oms);
    }

    if (lane == 0) {
        float H = meta[0], W = meta[1], scale = meta[2];
        const float* p = props + (size_t)warp * 4;
        float x1 = p[0] / scale, y1 = p[1] / scale;
        float x2 = p[2] / scale, y2 = p[3] / scale;
        float w  = x2 - x1 + 1.0f, h = y2 - y1 + 1.0f;
        float cx = x1 + 0.5f * w, cy = y1 + 0.5f * h;

        const float* d = deltas + (size_t)warp * (4 * N_CLS) + bc * 4;
        float pcx = d[0] * w + cx;
        float pcy = d[1] * h + cy;
        float pw  = expf(d[2]) * w;
        float ph  = expf(d[3]) * h;

        float px1 = pcx - 0.5f * pw, py1 = pcy - 0.5f * ph;
        float px2 = pcx + 0.5f * pw, py2 = pcy + 0.5f * ph;
        px1 = fminf(fmaxf(px1, 0.0f), W - 1.0f);
        py1 = fminf(fmaxf(py1, 0.0f), H - 1.0f);
        px2 = fminf(fmaxf(px2, 0.0f), W - 1.0f);
        py2 = fminf(fmaxf(py2, 0.0f), H - 1.0f);

        g_pbox[warp] = make_float4(px1, py1, px2, py2);
        g_nscore[warp] = ms;
    }
}

__device__ __forceinline__ bool iou_sup(float4 a, float aa, float4 b, float ba)
{
    float xx1 = fmaxf(a.x, b.x);
    float yy1 = fmaxf(a.y, b.y);
    float xx2 = fminf(a.z, b.z);
    float yy2 = fminf(a.w, b.w);
    float iw = fmaxf(xx2 - xx1 + 1.0f, 0.0f);
    float ih = fmaxf(yy2 - yy1 + 1.0f, 0.0f);
    float inter = iw * ih;
    return inter / (aa + ba - inter) > NMS_THRESH;
}

// warp-0 hierarchical suffix search over 65536-bucket histogram.
__device__ __forceinline__ void warp_select(const unsigned* hist, const unsigned* s1,
                                            unsigned target,
                                            volatile unsigned* s_b,
                                            volatile unsigned* s_above,
                                            volatile int* s_all)
{
    int lane = threadIdx.x;   // caller guarantees tid < 32

    unsigned s2 = 0;
    #pragma unroll 8
    for (int q = 0; q < 32; q++) s2 += s1[lane * 32 + q];
    unsigned incl = s2;
    #pragma unroll
    for (int off = 1; off < 32; off <<= 1) {
        unsigned v = __shfl_down_sync(0xffffffffu, incl, off);
        if (lane + off < 32) incl += v;
    }
    unsigned total = __shfl_sync(0xffffffffu, incl, 0);
    if (total < target) { if (lane == 0) *s_all = 1; return; }
    if (lane == 0) *s_all = 0;

    unsigned bal = __ballot_sync(0xffffffffu, incl >= target);
    int L1 = 31 - __clz(bal);
    unsigned carry1 = __shfl_sync(0xffffffffu, incl, (L1 + 1) & 31);
    if (L1 == 31) carry1 = 0;

    incl = s1[L1 * 32 + lane];
    #pragma unroll
    for (int off = 1; off < 32; off <<= 1) {
        unsigned v = __shfl_down_sync(0xffffffffu, incl, off);
        if (lane + off < 32) incl += v;
    }
    bal = __ballot_sync(0xffffffffu, carry1 + incl >= target);
    int L2 = 31 - __clz(bal);
    unsigned carry2 = __shfl_sync(0xffffffffu, incl, (L2 + 1) & 31);
    if (L2 == 31) carry2 = 0;
    carry2 += carry1;

    int bbase = (L1 * 32 + L2) * 64;
    unsigned w = hist[(bbase >> 1) + lane];
    unsigned lowc = w & 0xFFFFu, highc = w >> 16;
    incl = lowc + highc;
    #pragma unroll
    for (int off = 1; off < 32; off <<= 1) {
        unsigned v = __shfl_down_sync(0xffffffffu, incl, off);
        if (lane + off < 32) incl += v;
    }
    bal = __ballot_sync(0xffffffffu, carry2 + incl >= target);
    int L3 = 31 - __clz(bal);
    unsigned carryn = __shfl_sync(0xffffffffu, incl, (L3 + 1) & 31);
    if (L3 == 31) carryn = 0;
    carryn += carry2;

    if (lane == L3) {
        unsigned b, ab;
        if (carryn + highc >= target) { b = (unsigned)(bbase + 2 * L3 + 1); ab = carryn; }
        else                          { b = (unsigned)(bbase + 2 * L3);     ab = carryn + highc; }
        *s_b = b; *s_above = ab;
    }
}

// two-pass radix select over [0, hi]; returns lo (inclusive) s.t. count(bits in [lo,hi]) >= target
// (or takes everything if fewer remain). Block-wide; uses hist/s1/scalars smem.
__device__ unsigned radix_threshold(unsigned* hist, unsigned* s1, unsigned hi, unsigned target,
                                    volatile unsigned* s_b, volatile unsigned* s_above,
                                    volatile int* s_all)
{
    const int tid = threadIdx.x;
    for (int i = tid; i < 32768; i += T) hist[i] = 0;
    __syncthreads();
    for (int i = tid; i < N_ANCH; i += T) {
        unsigned bits = __float_as_uint(g_nscore[i]);
        if (bits <= hi) {
            unsigned b = bits >> 16;
            atomicAdd(&hist[b >> 1], 1u << ((b & 1) * 16));
        }
    }
    __syncthreads();
    {
        unsigned s = 0;
        #pragma unroll 8
        for (int q = 0; q < 32; q++) { unsigned w = hist[tid * 32 + q]; s += (w & 0xFFFFu) + (w >> 16); }
        s1[tid] = s;
    }
    __syncthreads();
    if (tid < 32) warp_select(hist, s1, target, s_b, s_above, s_all);
    __syncthreads();

    unsigned lo;
    if (*s_all) {
        lo = 0u;
    } else {
        unsigned b1  = *s_b;
        unsigned chi = *s_above;
        __syncthreads();
        for (int i = tid; i < 32768; i += T) hist[i] = 0;
        __syncthreads();
        for (int i = tid; i < N_ANCH; i += T) {
            unsigned bits = __float_as_uint(g_nscore[i]);
            if (bits <= hi && (bits >> 16) == b1) {
                unsigned b = bits & 0xFFFFu;
                atomicAdd(&hist[b >> 1], 1u << ((b & 1) * 16));
            }
        }
        __syncthreads();
        {
            unsigned s = 0;
            #pragma unroll 8
            for (int q = 0; q < 32; q++) { unsigned w = hist[tid * 32 + q]; s += (w & 0xFFFFu) + (w >> 16); }
            s1[tid] = s;
        }
        __syncthreads();
        if (tid < 32) warp_select(hist, s1, target - chi, s_b, s_above, s_all);
        __syncthreads();
        lo = (*s_all) ? (b1 << 16) : ((b1 << 16) | *s_b);
    }
    __syncthreads();
    return lo;
}

// collect bits in [lo,hi] into keys, pad & bitonic-sort descending; returns S (count).
__device__ int collect_sort(unsigned long long* keys, unsigned lo, unsigned hi,
                            volatile unsigned* s_cnt)
{
    const int tid = threadIdx.x;
    if (tid == 0) *s_cnt = 0;
    __syncthreads();
    for (int i = tid; i < N_ANCH; i += T) {
        unsigned bits = __float_as_uint(g_nscore[i]);
        if (bits >= lo && bits <= hi) {
            unsigned p = atomicAdd((unsigned*)s_cnt, 1u);
            if (p < KEYCAP)
                keys[p] = ((unsigned long long)bits << 32) | (0xFFFFFFFFu - (unsigned)i);
        }
    }
    __syncthreads();
    int S = min((int)*s_cnt, KEYCAP);
    int nsort = 1024;
    while (nsort < S) nsort <<= 1;
    for (int i = tid; i < nsort; i += T) if (i >= S) keys[i] = 0ull;
    __syncthreads();

    for (int k = 2; k <= nsort; k <<= 1) {
        for (int j = k >> 1; j > 0; j >>= 1) {
            for (int i = tid; i < nsort; i += T) {
                int ixj = i ^ j;
                if (ixj > i) {
                    unsigned long long a = keys[i], b = keys[ixj];
                    bool up = ((i & k) == 0);
                    if (up ? (a < b) : (a > b)) { keys[i] = b; keys[ixj] = a; }
                }
            }
            __syncthreads();
        }
    }
    return S;
}

// process one sorted chunk: sprev vs kept, (optional) matrix build, serial resolve.
// caller must have loaded cbox/carea/cidx and synced. returns updated kept.
__device__ int nms_chunk(int cn, int kept, bool build_mat,
                         float4* cbox, float* carea, unsigned* sprev, unsigned* cidx,
                         unsigned* mat, float4* kbox, float* karea, volatile int* s_kept)
{
    const int tid = threadIdx.x;
    const int lane = tid & 31;

    if (kept == 0) {
        for (int c = tid; c < cn; c += T) sprev[c] = 0;
    } else {
        for (int c = tid; c < cn; c += T) {
            float4 b = cbox[c]; float ba = carea[c];
            unsigned f = 0;
            for (int q = 0; q < kept; q++)
                if (iou_sup(kbox[q], karea[q], b, ba)) { f = 1; break; }
            sprev[c] = f;
        }
    }

    if (build_mat) {
        for (int iw = tid; iw < CH * 16; iw += T) {
            int i = iw & (CH - 1);
            int w = iw >> 9;
            int j0 = w << 5;
            if (i < cn && j0 < i) {
                float4 bi = cbox[i]; float ai = carea[i];
                int jmax = min(i, j0 + 32);
                unsigned word = 0;
                for (int j = j0; j < jmax; j++)
                    if (iou_sup(cbox[j], carea[j], bi, ai)) word |= 1u << (j - j0);
                mat[w * MAT_STRIDE + i] = word;
            } else if (i < cn) {
                mat[w * MAT_STRIDE + i] = 0u;
            }
        }
    }
    __syncthreads();

    if (tid < 32) {
        unsigned km = 0;
        int kp = kept;
        unsigned row = (lane < 16 && cn > 0) ? mat[lane * MAT_STRIDE] : 0u;
        for (int i = 0; i < cn && kp < PAD; i++) {
            unsigned nrow = (lane < 16 && i + 1 < cn) ? mat[lane * MAT_STRIDE + i + 1] : 0u;
            unsigned sp = sprev[i];
            bool clash = __any_sync(0xffffffffu, (row & km) != 0u) || (sp != 0u);
            if (!clash) {
                if (lane == 0) {
                    g_idx[kp]   = (int)cidx[i];
                    g_valid[kp] = 1.0f;
                    kbox[kp]    = cbox[i];
                    karea[kp]   = carea[i];
                }
                if (lane == (i >> 5)) km |= 1u << (i & 31);
                kp++;
            }
            row = nrow;
        }
        if (lane == 0) *s_kept = kp;
    }
    __syncthreads();
    return *s_kept;
}

// ---------------- kernel 2a: radix select + sort top batch (1 block) ----------------
__global__ __launch_bounds__(T, 1) void k_select()
{
    extern __shared__ char sm[];
    unsigned*           hist = (unsigned*)(sm);
    unsigned long long* keys = (unsigned long long*)(sm + OFF_KEYS);
    unsigned*           s1   = (unsigned*)(sm + OFF_S1);
    volatile unsigned*  s_cnt   = (volatile unsigned*)(sm + OFF_SCAL);
    volatile unsigned*  s_b     = (volatile unsigned*)(sm + OFF_SCAL + 8);
    volatile unsigned*  s_above = (volatile unsigned*)(sm + OFF_SCAL + 12);
    volatile int*       s_all   = (volatile int*)(sm + OFF_SCAL + 16);

    const int tid = threadIdx.x;

    unsigned lo = radix_threshold(hist, s1, 0xFFFFFFFFu, TARGET, s_b, s_above, s_all);
    int S = collect_sort(keys, lo, 0xFFFFFFFFu, s_cnt);

    for (int i = tid; i < S; i += T) g_skeys[i] = keys[i];
    for (int i = tid; i < 16 * 512; i += T) g_mat[i] = 0u;
    if (tid == 0) { g_S = S; g_lo = lo; }
}

// ---------------- kernel 2b: suppression bitmatrix on the full chip ----------------
__global__ void k_matrix()
{
    int id = blockIdx.x * blockDim.x + threadIdx.x;   // 8192 threads: cell (i, w)
    int i = id & 511;
    int w = id >> 9;
    int cn = min(g_S, CH);
    if (i >= cn) return;
    int j0 = w << 5;
    if (j0 >= i) return;

    unsigned idx_i = 0xFFFFFFFFu - (unsigned)g_skeys[i];
    float4 bi = g_pbox[idx_i];
    float  ai = (bi.z - bi.x + 1.0f) * (bi.w - bi.y + 1.0f);

    int jmax = min(i, j0 + 32);
    unsigned word = 0;
    for (int j = j0; j < jmax; j++) {
        unsigned idx_j = 0xFFFFFFFFu - (unsigned)g_skeys[j];
        float4 bj = g_pbox[idx_j];
        float  aj = (bj.z - bj.x + 1.0f) * (bj.w - bj.y + 1.0f);
        if (iou_sup(bj, aj, bi, ai)) word |= 1u << (j - j0);
    }
    g_mat[w * 512 + i] = word;
}

// ---------------- kernel 2c: serial resolve + (never-taken) general fallback ----------------
__global__ __launch_bounds__(T, 1) void k_resolve()
{
    extern __shared__ char sm[];
    unsigned*           hist  = (unsigned*)(sm);
    float4*             cbox  = (float4*)(sm);
    float*              carea = (float*)(sm + 8192);
    unsigned*           sprev = (unsigned*)(sm + 10240);
    unsigned*           cidx  = (unsigned*)(sm + 12288);
    unsigned*           mat   = (unsigned*)(sm + 14336);
    unsigned long long* keys  = (unsigned long long*)(sm + OFF_KEYS);
    unsigned*           s1    = (unsigned*)(sm + OFF_S1);
    float4*             kbox  = (float4*)(sm + OFF_KBOX);
    float*              karea = (float*)(sm + OFF_KAREA);
    volatile unsigned*  s_cnt   = (volatile unsigned*)(sm + OFF_SCAL);
    volatile int*       s_kept  = (volatile int*)(sm + OFF_SCAL + 4);
    volatile unsigned*  s_b     = (volatile unsigned*)(sm + OFF_SCAL + 8);
    volatile unsigned*  s_above = (volatile unsigned*)(sm + OFF_SCAL + 12);
    volatile int*       s_all   = (volatile int*)(sm + OFF_SCAL + 16);

    const int tid = threadIdx.x;

    if (tid == 0) *s_kept = 0;
    __syncthreads();
    int kept = 0;

    // ---- phase A: sorted batch from k_select; chunk 0's matrix is precomputed ----
    int S = g_S;
    unsigned lo0 = g_lo;
    for (int base = 0; base < S && kept < PAD; base += CH) {
        int cn = min(CH, S - base);
        for (int c = tid; c < cn; c += T) {
            unsigned idx = 0xFFFFFFFFu - (unsigned)g_skeys[base + c];
            cidx[c] = idx;
            float4 b = g_pbox[idx];
            cbox[c] = b;
            carea[c] = (b.z - b.x + 1.0f) * (b.w - b.y + 1.0f);
        }
        if (base == 0) {
            for (int iw = tid; iw < CH * 16; iw += T) {
                int i = iw & (CH - 1);
                int w = iw >> 9;
                if (i < cn) mat[w * MAT_STRIDE + i] = g_mat[w * 512 + i];
            }
        }
        __syncthreads();
        kept = nms_chunk(cn, kept, base != 0, cbox, carea, sprev, cidx, mat,
                         kbox, karea, s_kept);
    }

    // ---- phase B: general continuation (rarely/never taken) ----
    if (kept < PAD && lo0 > 0) {
        unsigned hi = lo0 - 1u;
        while (kept < PAD) {
            unsigned lo = radix_threshold(hist, s1, hi, TARGET, s_b, s_above, s_all);
            int Sb = collect_sort(keys, lo, hi, s_cnt);
            for (int base = 0; base < Sb && kept < PAD; base += CH) {
                int cn = min(CH, Sb - base);
                for (int c = tid; c < cn; c += T) {
                    unsigned idx = 0xFFFFFFFFu - (unsigned)keys[base + c];
                    cidx[c] = idx;
                    float4 b = g_pbox[idx];
                    cbox[c] = b;
                    carea[c] = (b.z - b.x + 1.0f) * (b.w - b.y + 1.0f);
                }
                __syncthreads();
                kept = nms_chunk(cn, kept, true, cbox, carea, sprev, cidx, mat,
                                 kbox, karea, s_kept);
            }
            if (lo == 0u) break;
            hi = lo - 1u;
            __syncthreads();
        }
    }

    for (int r = kept + tid; r < PAD; r += T) { g_idx[r] = 0; g_valid[r] = 0.0f; }
}

// ---------------- kernel 3: gather outputs ----------------
#define OFF_SC  (PAD * 4)
#define OFF_MK  (OFF_SC + PAD * N_CLS)

__global__ void k_gather_small(const float* __restrict__ scores,
                               float* __restrict__ out)
{
    int e = blockIdx.x * blockDim.x + threadIdx.x;
    if (e >= OFF_MK) return;
    if (e < OFF_SC) {
        int k = e >> 2, c = e & 3;
        const float* bp = (const float*)&g_pbox[g_idx[k]];
        out[e] = bp[c] * g_valid[k];
    } else {
        int r = e - OFF_SC;
        int k = r / N_CLS, c = r - k * N_CLS;
        out[e] = scores[(size_t)g_idx[k] * N_CLS + c] * g_valid[k];
    }
}

__global__ void k_gather_masks(const float* __restrict__ masks,
                               float* __restrict__ out)
{
    const int per = MASK_SZ / 4;  // 3969 float4 per detection
    int e = blockIdx.x * blockDim.x + threadIdx.x;
    if (e >= PAD * per) return;
    int k = e / per, m = e - k * per;
    const float4* src = (const float4*)(masks + (size_t)g_idx[k] * MASK_SZ);
    float4 v = src[m];
    float s = g_valid[k];
    v.x *= s; v.y *= s; v.z *= s; v.w *= s;
    ((float4*)(out + OFF_MK))[e] = v;
}

// ---------------- launch ----------------
extern "C" void kernel_launch(void* const* d_in, const int* in_sizes, int n_in,
                              void* d_out, int out_size)
{
    const float* meta   = (const float*)d_in[0];
    const float* deltas = (const float*)d_in[1];
    const float* props  = (const float*)d_in[2];
    const float* scores = (const float*)d_in[3];
    const float* masks  = (const float*)d_in[4];
    float* out = (float*)d_out;

    static bool attr_done = false;
    if (!attr_done) {
        cudaFuncSetAttribute(k_select,  cudaFuncAttributeMaxDynamicSharedMemorySize, SMEM_TOTAL);
        cudaFuncSetAttribute(k_resolve, cudaFuncAttributeMaxDynamicSharedMemorySize, SMEM_TOTAL);
        attr_done = true;
    }

    k_decode<<<(N_ANCH + 3) / 4, 128>>>(meta, deltas, props, scores);
    k_select<<<1, T, SMEM_TOTAL>>>();
    k_matrix<<<32, 256>>>();
    k_resolve<<<1, T, SMEM_TOTAL>>>();
    k_gather_small<<<(OFF_MK + 255) / 256, 256>>>(scores, out);
    k_gather_masks<<<(PAD * (MASK_SZ / 4) + 255) / 256, 256>>>(masks, out);
}

// round 6
// speedup vs baseline: 10.2063x; 1.7306x over previous
#include <cuda_runtime.h>
#include <cuda_bf16.h>
#include <math.h>

#define N_ANCH 6000
#define N_CLS  81
#define PAD    300
#define MASK_SZ (14*14*81)   // 15876
#define NMS_THRESH 0.5f
#define T      1024
#define TARGET 512u
#define KEYCAP 8192
#define CH     512
#define MAT_STRIDE 516

// ---- dynamic smem layout (bytes), shared by k_select / k_resolve ----
#define OFF_KEYS  131072   // u64[8192]  (65536) -> 196608
#define OFF_S1    196608   // u32[1024]  (4096)  -> 200704
#define OFF_KBOX  200704   // float4[300](4800)  -> 205504
#define OFF_KAREA 205504   // f32[300]   (1200)  -> 206704
#define OFF_SCAL  206704
#define SMEM_TOTAL 206848
// region A aliases (resolve phases):
//   cbox f4[512]@0 (8192) | carea f32[512]@8192 | sprev u32[512]@10240
//   cidx u32[512]@12288 | mat u32[16*516]@14336 (33024)
//   smat u32[16*512]@47360 (32768)  -- fast-resolve matrix copy
//   scidx u32[512]@80128 (2048)

// ---------------- scratch (device globals, no allocation) ----------------
__device__ float4 g_pbox[N_ANCH];
__device__ float  g_nscore[N_ANCH];
__device__ unsigned long long g_skeys[KEYCAP];
__device__ int      g_S;
__device__ unsigned g_lo;
__device__ unsigned g_mat[16 * 512];
__device__ int    g_idx[PAD];
__device__ float  g_valid[PAD];

// ---------------- kernel 1: per-anchor argmax + box decode ----------------
__global__ void k_decode(const float* __restrict__ meta,
                         const float* __restrict__ deltas,
                         const float* __restrict__ props,
                         const float* __restrict__ scores)
{
    int warp = (blockIdx.x * blockDim.x + threadIdx.x) >> 5;
    int lane = threadIdx.x & 31;
    if (warp >= N_ANCH) return;

    const float* srow = scores + (size_t)warp * N_CLS;
    float bv = -INFINITY; int bc = 0;
    float ms = -INFINITY;
    for (int c = lane; c < N_CLS; c += 32) {
        float v = srow[c];
        if (v > bv) { bv = v; bc = c; }
        if (c >= 1) ms = fmaxf(ms, v);
    }
    #pragma unroll
    for (int off = 16; off; off >>= 1) {
        float ov  = __shfl_down_sync(0xffffffffu, bv, off);
        int   oc  = __shfl_down_sync(0xffffffffu, bc, off);
        float oms = __shfl_down_sync(0xffffffffu, ms, off);
        if (ov > bv || (ov == bv && oc < bc)) { bv = ov; bc = oc; }
        ms = fmaxf(ms, oms);
    }

    if (lane == 0) {
        float H = meta[0], W = meta[1], scale = meta[2];
        const float* p = props + (size_t)warp * 4;
        float x1 = p[0] / scale, y1 = p[1] / scale;
        float x2 = p[2] / scale, y2 = p[3] / scale;
        float w  = x2 - x1 + 1.0f, h = y2 - y1 + 1.0f;
        float cx = x1 + 0.5f * w, cy = y1 + 0.5f * h;

        const float* d = deltas + (size_t)warp * (4 * N_CLS) + bc * 4;
        float pcx = d[0] * w + cx;
        float pcy = d[1] * h + cy;
        float pw  = expf(d[2]) * w;
        float ph  = expf(d[3]) * h;

        float px1 = pcx - 0.5f * pw, py1 = pcy - 0.5f * ph;
        float px2 = pcx + 0.5f * pw, py2 = pcy + 0.5f * ph;
        px1 = fminf(fmaxf(px1, 0.0f), W - 1.0f);
        py1 = fminf(fmaxf(py1, 0.0f), H - 1.0f);
        px2 = fminf(fmaxf(px2, 0.0f), W - 1.0f);
        py2 = fminf(fmaxf(py2, 0.0f), H - 1.0f);

        g_pbox[warp] = make_float4(px1, py1, px2, py2);
        g_nscore[warp] = ms;
    }
}

__device__ __forceinline__ bool iou_sup(float4 a, float aa, float4 b, float ba)
{
    float xx1 = fmaxf(a.x, b.x);
    float yy1 = fmaxf(a.y, b.y);
    float xx2 = fminf(a.z, b.z);
    float yy2 = fminf(a.w, b.w);
    float iw = fmaxf(xx2 - xx1 + 1.0f, 0.0f);
    float ih = fmaxf(yy2 - yy1 + 1.0f, 0.0f);
    float inter = iw * ih;
    return inter / (aa + ba - inter) > NMS_THRESH;
}

// warp-0 hierarchical suffix search over 65536-bucket histogram.
__device__ __forceinline__ void warp_select(const unsigned* hist, const unsigned* s1,
                                            unsigned target,
                                            volatile unsigned* s_b,
                                            volatile unsigned* s_above,
                                            volatile int* s_all)
{
    int lane = threadIdx.x;

    unsigned s2 = 0;
    #pragma unroll 8
    for (int q = 0; q < 32; q++) s2 += s1[lane * 32 + q];
    unsigned incl = s2;
    #pragma unroll
    for (int off = 1; off < 32; off <<= 1) {
        unsigned v = __shfl_down_sync(0xffffffffu, incl, off);
        if (lane + off < 32) incl += v;
    }
    unsigned total = __shfl_sync(0xffffffffu, incl, 0);
    if (total < target) { if (lane == 0) *s_all = 1; return; }
    if (lane == 0) *s_all = 0;

    unsigned bal = __ballot_sync(0xffffffffu, incl >= target);
    int L1 = 31 - __clz(bal);
    unsigned carry1 = __shfl_sync(0xffffffffu, incl, (L1 + 1) & 31);
    if (L1 == 31) carry1 = 0;

    incl = s1[L1 * 32 + lane];
    #pragma unroll
    for (int off = 1; off < 32; off <<= 1) {
        unsigned v = __shfl_down_sync(0xffffffffu, incl, off);
        if (lane + off < 32) incl += v;
    }
    bal = __ballot_sync(0xffffffffu, carry1 + incl >= target);
    int L2 = 31 - __clz(bal);
    unsigned carry2 = __shfl_sync(0xffffffffu, incl, (L2 + 1) & 31);
    if (L2 == 31) carry2 = 0;
    carry2 += carry1;

    int bbase = (L1 * 32 + L2) * 64;
    unsigned w = hist[(bbase >> 1) + lane];
    unsigned lowc = w & 0xFFFFu, highc = w >> 16;
    incl = lowc + highc;
    #pragma unroll
    for (int off = 1; off < 32; off <<= 1) {
        unsigned v = __shfl_down_sync(0xffffffffu, incl, off);
        if (lane + off < 32) incl += v;
    }
    bal = __ballot_sync(0xffffffffu, carry2 + incl >= target);
    int L3 = 31 - __clz(bal);
    unsigned carryn = __shfl_sync(0xffffffffu, incl, (L3 + 1) & 31);
    if (L3 == 31) carryn = 0;
    carryn += carry2;

    if (lane == L3) {
        unsigned b, ab;
        if (carryn + highc >= target) { b = (unsigned)(bbase + 2 * L3 + 1); ab = carryn; }
        else                          { b = (unsigned)(bbase + 2 * L3);     ab = carryn + highc; }
        *s_b = b; *s_above = ab;
    }
}

__device__ unsigned radix_threshold(unsigned* hist, unsigned* s1, unsigned hi, unsigned target,
                                    volatile unsigned* s_b, volatile unsigned* s_above,
                                    volatile int* s_all)
{
    const int tid = threadIdx.x;
    for (int i = tid; i < 32768; i += T) hist[i] = 0;
    __syncthreads();
    for (int i = tid; i < N_ANCH; i += T) {
        unsigned bits = __float_as_uint(g_nscore[i]);
        if (bits <= hi) {
            unsigned b = bits >> 16;
            atomicAdd(&hist[b >> 1], 1u << ((b & 1) * 16));
        }
    }
    __syncthreads();
    {
        unsigned s = 0;
        #pragma unroll 8
        for (int q = 0; q < 32; q++) { unsigned w = hist[tid * 32 + q]; s += (w & 0xFFFFu) + (w >> 16); }
        s1[tid] = s;
    }
    __syncthreads();
    if (tid < 32) warp_select(hist, s1, target, s_b, s_above, s_all);
    __syncthreads();

    unsigned lo;
    if (*s_all) {
        lo = 0u;
    } else {
        unsigned b1  = *s_b;
        unsigned chi = *s_above;
        __syncthreads();
        for (int i = tid; i < 32768; i += T) hist[i] = 0;
        __syncthreads();
        for (int i = tid; i < N_ANCH; i += T) {
            unsigned bits = __float_as_uint(g_nscore[i]);
            if (bits <= hi && (bits >> 16) == b1) {
                unsigned b = bits & 0xFFFFu;
                atomicAdd(&hist[b >> 1], 1u << ((b & 1) * 16));
            }
        }
        __syncthreads();
        {
            unsigned s = 0;
            #pragma unroll 8
            for (int q = 0; q < 32; q++) { unsigned w = hist[tid * 32 + q]; s += (w & 0xFFFFu) + (w >> 16); }
            s1[tid] = s;
        }
        __syncthreads();
        if (tid < 32) warp_select(hist, s1, target - chi, s_b, s_above, s_all);
        __syncthreads();
        lo = (*s_all) ? (b1 << 16) : ((b1 << 16) | *s_b);
    }
    __syncthreads();
    return lo;
}

__device__ int collect_sort(unsigned long long* keys, unsigned lo, unsigned hi,
                            volatile unsigned* s_cnt)
{
    const int tid = threadIdx.x;
    if (tid == 0) *s_cnt = 0;
    __syncthreads();
    for (int i = tid; i < N_ANCH; i += T) {
        unsigned bits = __float_as_uint(g_nscore[i]);
        if (bits >= lo && bits <= hi) {
            unsigned p = atomicAdd((unsigned*)s_cnt, 1u);
            if (p < KEYCAP)
                keys[p] = ((unsigned long long)bits << 32) | (0xFFFFFFFFu - (unsigned)i);
        }
    }
    __syncthreads();
    int S = min((int)*s_cnt, KEYCAP);
    int nsort = 1024;
    while (nsort < S) nsort <<= 1;
    for (int i = tid; i < nsort; i += T) if (i >= S) keys[i] = 0ull;
    __syncthreads();

    for (int k = 2; k <= nsort; k <<= 1) {
        for (int j = k >> 1; j > 0; j >>= 1) {
            for (int i = tid; i < nsort; i += T) {
                int ixj = i ^ j;
                if (ixj > i) {
                    unsigned long long a = keys[i], b = keys[ixj];
                    bool up = ((i & k) == 0);
                    if (up ? (a < b) : (a > b)) { keys[i] = b; keys[ixj] = a; }
                }
            }
            __syncthreads();
        }
    }
    return S;
}

// general (slow-path) chunk processor — only used beyond the first 512 candidates
__device__ int nms_chunk(int cn, int kept, bool build_mat,
                         float4* cbox, float* carea, unsigned* sprev, unsigned* cidx,
                         unsigned* mat, float4* kbox, float* karea, volatile int* s_kept)
{
    const int tid = threadIdx.x;
    const int lane = tid & 31;

    if (kept == 0) {
        for (int c = tid; c < cn; c += T) sprev[c] = 0;
    } else {
        for (int c = tid; c < cn; c += T) {
            float4 b = cbox[c]; float ba = carea[c];
            unsigned f = 0;
            for (int q = 0; q < kept; q++)
                if (iou_sup(kbox[q], karea[q], b, ba)) { f = 1; break; }
            sprev[c] = f;
        }
    }

    if (build_mat) {
        for (int iw = tid; iw < CH * 16; iw += T) {
            int i = iw & (CH - 1);
            int w = iw >> 9;
            int j0 = w << 5;
            if (i < cn && j0 < i) {
                float4 bi = cbox[i]; float ai = carea[i];
                int jmax = min(i, j0 + 32);
                unsigned word = 0;
                for (int j = j0; j < jmax; j++)
                    if (iou_sup(cbox[j], carea[j], bi, ai)) word |= 1u << (j - j0);
                mat[w * MAT_STRIDE + i] = word;
            } else if (i < cn) {
                mat[w * MAT_STRIDE + i] = 0u;
            }
        }
    }
    __syncthreads();

    if (tid < 32) {
        unsigned km = 0;
        int kp = kept;
        unsigned row = (lane < 16 && cn > 0) ? mat[lane * MAT_STRIDE] : 0u;
        for (int i = 0; i < cn && kp < PAD; i++) {
            unsigned nrow = (lane < 16 && i + 1 < cn) ? mat[lane * MAT_STRIDE + i + 1] : 0u;
            unsigned sp = sprev[i];
            bool clash = __any_sync(0xffffffffu, (row & km) != 0u) || (sp != 0u);
            if (!clash) {
                if (lane == 0) {
                    g_idx[kp]   = (int)cidx[i];
                    g_valid[kp] = 1.0f;
                    kbox[kp]    = cbox[i];
                    karea[kp]   = carea[i];
                }
                if (lane == (i >> 5)) km |= 1u << (i & 31);
                kp++;
            }
            row = nrow;
        }
        if (lane == 0) *s_kept = kp;
    }
    __syncthreads();
    return *s_kept;
}

// ---------------- kernel 2a: radix select + sort top batch (1 block) ----------------
__global__ __launch_bounds__(T, 1) void k_select()
{
    extern __shared__ char sm[];
    unsigned*           hist = (unsigned*)(sm);
    unsigned long long* keys = (unsigned long long*)(sm + OFF_KEYS);
    unsigned*           s1   = (unsigned*)(sm + OFF_S1);
    volatile unsigned*  s_cnt   = (volatile unsigned*)(sm + OFF_SCAL);
    volatile unsigned*  s_b     = (volatile unsigned*)(sm + OFF_SCAL + 8);
    volatile unsigned*  s_above = (volatile unsigned*)(sm + OFF_SCAL + 12);
    volatile int*       s_all   = (volatile int*)(sm + OFF_SCAL + 16);

    const int tid = threadIdx.x;

    unsigned lo = radix_threshold(hist, s1, 0xFFFFFFFFu, TARGET, s_b, s_above, s_all);
    int S = collect_sort(keys, lo, 0xFFFFFFFFu, s_cnt);

    for (int i = tid; i < S; i += T) g_skeys[i] = keys[i];
    for (int i = tid; i < 16 * 512; i += T) g_mat[i] = 0u;
    if (tid == 0) { g_S = S; g_lo = lo; }
}

// ---------------- kernel 2b: suppression bitmatrix on the full chip ----------------
__global__ void k_matrix()
{
    int id = blockIdx.x * blockDim.x + threadIdx.x;   // 8192 threads: cell (i, w)
    int i = id & 511;
    int w = id >> 9;
    int cn = min(g_S, CH);
    if (i >= cn) return;
    int j0 = w << 5;
    if (j0 >= i) return;

    unsigned idx_i = 0xFFFFFFFFu - (unsigned)g_skeys[i];
    float4 bi = g_pbox[idx_i];
    float  ai = (bi.z - bi.x + 1.0f) * (bi.w - bi.y + 1.0f);

    int jmax = min(i, j0 + 32);
    unsigned word = 0;
    for (int j = j0; j < jmax; j++) {
        unsigned idx_j = 0xFFFFFFFFu - (unsigned)g_skeys[j];
        float4 bj = g_pbox[idx_j];
        float  aj = (bj.z - bj.x + 1.0f) * (bj.w - bj.y + 1.0f);
        if (iou_sup(bj, aj, bi, ai)) word |= 1u << (j - j0);
    }
    g_mat[w * 512 + i] = word;
}

// ---------------- kernel 2c: fast group-wise resolve + general fallback ----------------
__global__ __launch_bounds__(T, 1) void k_resolve()
{
    extern __shared__ char sm[];
    unsigned*           hist  = (unsigned*)(sm);
    float4*             cbox  = (float4*)(sm);
    float*              carea = (float*)(sm + 8192);
    unsigned*           sprev = (unsigned*)(sm + 10240);
    unsigned*           cidx  = (unsigned*)(sm + 12288);
    unsigned*           mat   = (unsigned*)(sm + 14336);
    unsigned*           smat  = (unsigned*)(sm + 47360);   // [16][512]
    unsigned*           scidx = (unsigned*)(sm + 80128);   // [512]
    unsigned long long* keys  = (unsigned long long*)(sm + OFF_KEYS);
    unsigned*           s1    = (unsigned*)(sm + OFF_S1);
    float4*             kbox  = (float4*)(sm + OFF_KBOX);
    float*              karea = (float*)(sm + OFF_KAREA);
    volatile unsigned*  s_cnt   = (volatile unsigned*)(sm + OFF_SCAL);
    volatile int*       s_kept  = (volatile int*)(sm + OFF_SCAL + 4);
    volatile unsigned*  s_b     = (volatile unsigned*)(sm + OFF_SCAL + 8);
    volatile unsigned*  s_above = (volatile unsigned*)(sm + OFF_SCAL + 12);
    volatile int*       s_all   = (volatile int*)(sm + OFF_SCAL + 16);

    const int tid = threadIdx.x;
    const int lane = tid & 31;

    int S = g_S;
    int cn0 = min(S, CH);

    // preload matrix + candidate indices (all warps)
    for (int i = tid; i < 16 * 512; i += T) smat[i] = g_mat[i];
    for (int i = tid; i < cn0; i += T) scidx[i] = 0xFFFFFFFFu - (unsigned)g_skeys[i];
    if (tid == 0) *s_kept = 0;
    __syncthreads();

    // ---- fast resolve of first chunk: warp 0, 16 group-steps ----
    if (tid < 32) {
        unsigned km[16];
        #pragma unroll
        for (int g = 0; g < 16; g++) km[g] = 0u;
        int kp = 0;
        #pragma unroll
        for (int g = 0; g < 16; g++) {
            int i = g * 32 + lane;
            bool active = i < cn0;
            unsigned r = active ? smat[g * 512 + i] : 0u;       // intra-group bits j<i
            unsigned clash = 0;
            #pragma unroll
            for (int w = 0; w < 16; w++) {
                if (w >= g) break;
                clash |= (active ? smat[w * 512 + i] : 0u) & km[w];
            }
            unsigned myidx = active ? scidx[i] : 0u;
            unsigned cball = __ballot_sync(0xffffffffu, (clash != 0u) || !active);
            unsigned kmg = 0u;
            #pragma unroll
            for (int t = 0; t < 32; t++) {
                unsigned rt = __shfl_sync(0xffffffffu, r, t);
                bool keep = !((cball >> t) & 1u) && !(rt & kmg) && (kp < PAD);
                if (keep) {
                    if (lane == t) { g_idx[kp] = (int)myidx; g_valid[kp] = 1.0f; }
                    kmg |= 1u << t;
                    kp++;
                }
            }
            km[g] = kmg;
        }
        if (lane == 0) *s_kept = kp;
    }
    __syncthreads();
    int kept = *s_kept;

    // ---- general fallback (rare): more chunks in batch / further radix rounds ----
    if (kept < PAD && (S > CH || g_lo > 0)) {
        // reconstruct kept boxes from g_idx
        for (int q = tid; q < kept; q += T) {
            float4 b = g_pbox[g_idx[q]];
            kbox[q] = b;
            karea[q] = (b.z - b.x + 1.0f) * (b.w - b.y + 1.0f);
        }
        __syncthreads();

        for (int base = CH; base < S && kept < PAD; base += CH) {
            int cn = min(CH, S - base);
            for (int c = tid; c < cn; c += T) {
                unsigned idx = 0xFFFFFFFFu - (unsigned)g_skeys[base + c];
                cidx[c] = idx;
                float4 b = g_pbox[idx];
                cbox[c] = b;
                carea[c] = (b.z - b.x + 1.0f) * (b.w - b.y + 1.0f);
            }
            __syncthreads();
            kept = nms_chunk(cn, kept, true, cbox, carea, sprev, cidx, mat,
                             kbox, karea, s_kept);
        }

        if (kept < PAD && g_lo > 0) {
            unsigned hi = g_lo - 1u;
            while (kept < PAD) {
                unsigned lo = radix_threshold(hist, s1, hi, TARGET, s_b, s_above, s_all);
                int Sb = collect_sort(keys, lo, hi, s_cnt);
                for (int base = 0; base < Sb && kept < PAD; base += CH) {
                    int cn = min(CH, Sb - base);
                    for (int c = tid; c < cn; c += T) {
                        unsigned idx = 0xFFFFFFFFu - (unsigned)keys[base + c];
                        cidx[c] = idx;
                        float4 b = g_pbox[idx];
                        cbox[c] = b;
                        carea[c] = (b.z - b.x + 1.0f) * (b.w - b.y + 1.0f);
                    }
                    __syncthreads();
                    kept = nms_chunk(cn, kept, true, cbox, carea, sprev, cidx, mat,
                                     kbox, karea, s_kept);
                }
                if (lo == 0u) break;
                hi = lo - 1u;
                __syncthreads();
            }
        }
    }

    for (int r = kept + tid; r < PAD; r += T) { g_idx[r] = 0; g_valid[r] = 0.0f; }
}

// ---------------- kernel 3: merged gather ----------------
#define OFF_SC  (PAD * 4)
#define OFF_MK  (OFF_SC + PAD * N_CLS)
#define MK_F4   (PAD * (MASK_SZ / 4))          // 1190700 float4
#define GATHER_ELEMS (OFF_MK + MK_F4)

__global__ void k_gather(const float* __restrict__ scores,
                         const float* __restrict__ masks,
                         float* __restrict__ out)
{
    int e = blockIdx.x * blockDim.x + threadIdx.x;
    if (e < OFF_MK) {
        if (e < OFF_SC) {
            int k = e >> 2, c = e & 3;
            const float* bp = (const float*)&g_pbox[g_idx[k]];
            out[e] = bp[c] * g_valid[k];
        } else {
            int r = e - OFF_SC;
            int k = r / N_CLS, c = r - k * N_CLS;
            out[e] = scores[(size_t)g_idx[k] * N_CLS + c] * g_valid[k];
        }
    } else {
        int f = e - OFF_MK;
        if (f < MK_F4) {
            const int per = MASK_SZ / 4;
            int k = f / per, m = f - k * per;
            const float4* src = (const float4*)(masks + (size_t)g_idx[k] * MASK_SZ);
            float4 v = src[m];
            float s = g_valid[k];
            v.x *= s; v.y *= s; v.z *= s; v.w *= s;
            ((float4*)(out + OFF_MK))[f] = v;
        }
    }
}

// ---------------- launch ----------------
extern "C" void kernel_launch(void* const* d_in, const int* in_sizes, int n_in,
                              void* d_out, int out_size)
{
    const float* meta   = (const float*)d_in[0];
    const float* deltas = (const float*)d_in[1];
    const float* props  = (const float*)d_in[2];
    const float* scores = (const float*)d_in[3];
    const float* masks  = (const float*)d_in[4];
    float* out = (float*)d_out;

    static bool attr_done = false;
    if (!attr_done) {
        cudaFuncSetAttribute(k_select,  cudaFuncAttributeMaxDynamicSharedMemorySize, SMEM_TOTAL);
        cudaFuncSetAttribute(k_resolve, cudaFuncAttributeMaxDynamicSharedMemorySize, SMEM_TOTAL);
        attr_done = true;
    }

    k_decode<<<(N_ANCH + 3) / 4, 128>>>(meta, deltas, props, scores);
    k_select<<<1, T, SMEM_TOTAL>>>();
    k_matrix<<<32, 256>>>();
    k_resolve<<<1, T, SMEM_TOTAL>>>();
    k_gather<<<(GATHER_ELEMS + 255) / 256, 256>>>(scores, masks, out);
}

// round 7
// speedup vs baseline: 10.6025x; 1.0388x over previous
#include <cuda_runtime.h>
#include <cuda_bf16.h>
#include <math.h>

#define N_ANCH 6000
#define N_CLS  81
#define PAD    300
#define MASK_SZ (14*14*81)   // 15876
#define NMS_THRESH 0.5f
#define T      1024
#define TARGET 512u
#define KEYCAP 8192
#define CH     512
#define MAT_STRIDE 516

// ---- dynamic smem layout (bytes), shared by k_select / k_resolve ----
#define OFF_KEYS  131072   // u64[8192]  (65536) -> 196608
#define OFF_S1    196608   // u32[1024]  (4096)  -> 200704
#define OFF_KBOX  200704   // float4[300](4800)  -> 205504
#define OFF_KAREA 205504   // f32[300]   (1200)  -> 206704
#define OFF_SCAL  206704
#define SMEM_TOTAL 206848
// region A aliases (resolve phases):
//   cbox f4[512]@0 (8192) | carea f32[512]@8192 | sprev u32[512]@10240
//   cidx u32[512]@12288 | mat u32[16*516]@14336 (33024)
//   smat u32[16*512]@47360 (32768)  -- fast-resolve matrix copy
//   scidx u32[512]@80128 (2048)

// ---------------- scratch (device globals, no allocation) ----------------
__device__ float4 g_pbox[N_ANCH];
__device__ float  g_nscore[N_ANCH];
__device__ unsigned long long g_skeys[KEYCAP];
__device__ int      g_S;
__device__ unsigned g_lo;
__device__ unsigned g_mat[16 * 512];
__device__ int    g_idx[PAD];
__device__ float  g_valid[PAD];

// ---------------- kernel 1: per-anchor argmax + box decode ----------------
__global__ void k_decode(const float* __restrict__ meta,
                         const float* __restrict__ deltas,
                         const float* __restrict__ props,
                         const float* __restrict__ scores)
{
    int warp = (blockIdx.x * blockDim.x + threadIdx.x) >> 5;
    int lane = threadIdx.x & 31;
    if (warp >= N_ANCH) return;

    const float* srow = scores + (size_t)warp * N_CLS;
    float bv = -INFINITY; int bc = 0;
    float ms = -INFINITY;
    for (int c = lane; c < N_CLS; c += 32) {
        float v = srow[c];
        if (v > bv) { bv = v; bc = c; }
        if (c >= 1) ms = fmaxf(ms, v);
    }
    #pragma unroll
    for (int off = 16; off; off >>= 1) {
        float ov  = __shfl_down_sync(0xffffffffu, bv, off);
        int   oc  = __shfl_down_sync(0xffffffffu, bc, off);
        float oms = __shfl_down_sync(0xffffffffu, ms, off);
        if (ov > bv || (ov == bv && oc < bc)) { bv = ov; bc = oc; }
        ms = fmaxf(ms, oms);
    }

    if (lane == 0) {
        float H = meta[0], W = meta[1], scale = meta[2];
        const float* p = props + (size_t)warp * 4;
        float x1 = p[0] / scale, y1 = p[1] / scale;
        float x2 = p[2] / scale, y2 = p[3] / scale;
        float w  = x2 - x1 + 1.0f, h = y2 - y1 + 1.0f;
        float cx = x1 + 0.5f * w, cy = y1 + 0.5f * h;

        const float* d = deltas + (size_t)warp * (4 * N_CLS) + bc * 4;
        float pcx = d[0] * w + cx;
        float pcy = d[1] * h + cy;
        float pw  = expf(d[2]) * w;
        float ph  = expf(d[3]) * h;

        float px1 = pcx - 0.5f * pw, py1 = pcy - 0.5f * ph;
        float px2 = pcx + 0.5f * pw, py2 = pcy + 0.5f * ph;
        px1 = fminf(fmaxf(px1, 0.0f), W - 1.0f);
        py1 = fminf(fmaxf(py1, 0.0f), H - 1.0f);
        px2 = fminf(fmaxf(px2, 0.0f), W - 1.0f);
        py2 = fminf(fmaxf(py2, 0.0f), H - 1.0f);

        g_pbox[warp] = make_float4(px1, py1, px2, py2);
        g_nscore[warp] = ms;
    }
}

__device__ __forceinline__ bool iou_sup(float4 a, float aa, float4 b, float ba)
{
    float xx1 = fmaxf(a.x, b.x);
    float yy1 = fmaxf(a.y, b.y);
    float xx2 = fminf(a.z, b.z);
    float yy2 = fminf(a.w, b.w);
    float iw = fmaxf(xx2 - xx1 + 1.0f, 0.0f);
    float ih = fmaxf(yy2 - yy1 + 1.0f, 0.0f);
    float inter = iw * ih;
    return inter / (aa + ba - inter) > NMS_THRESH;
}

// warp-0 hierarchical suffix search over 65536-bucket histogram.
__device__ __forceinline__ void warp_select(const unsigned* hist, const unsigned* s1,
                                            unsigned target,
                                            volatile unsigned* s_b,
                                            volatile unsigned* s_above,
                                            volatile int* s_all)
{
    int lane = threadIdx.x;

    unsigned s2 = 0;
    #pragma unroll 8
    for (int q = 0; q < 32; q++) s2 += s1[lane * 32 + q];
    unsigned incl = s2;
    #pragma unroll
    for (int off = 1; off < 32; off <<= 1) {
        unsigned v = __shfl_down_sync(0xffffffffu, incl, off);
        if (lane + off < 32) incl += v;
    }
    unsigned total = __shfl_sync(0xffffffffu, incl, 0);
    if (total < target) { if (lane == 0) *s_all = 1; return; }
    if (lane == 0) *s_all = 0;

    unsigned bal = __ballot_sync(0xffffffffu, incl >= target);
    int L1 = 31 - __clz(bal);
    unsigned carry1 = __shfl_sync(0xffffffffu, incl, (L1 + 1) & 31);
    if (L1 == 31) carry1 = 0;

    incl = s1[L1 * 32 + lane];
    #pragma unroll
    for (int off = 1; off < 32; off <<= 1) {
        unsigned v = __shfl_down_sync(0xffffffffu, incl, off);
        if (lane + off < 32) incl += v;
    }
    bal = __ballot_sync(0xffffffffu, carry1 + incl >= target);
    int L2 = 31 - __clz(bal);
    unsigned carry2 = __shfl_sync(0xffffffffu, incl, (L2 + 1) & 31);
    if (L2 == 31) carry2 = 0;
    carry2 += carry1;

    int bbase = (L1 * 32 + L2) * 64;
    unsigned w = hist[(bbase >> 1) + lane];
    unsigned lowc = w & 0xFFFFu, highc = w >> 16;
    incl = lowc + highc;
    #pragma unroll
    for (int off = 1; off < 32; off <<= 1) {
        unsigned v = __shfl_down_sync(0xffffffffu, incl, off);
        if (lane + off < 32) incl += v;
    }
    bal = __ballot_sync(0xffffffffu, carry2 + incl >= target);
    int L3 = 31 - __clz(bal);
    unsigned carryn = __shfl_sync(0xffffffffu, incl, (L3 + 1) & 31);
    if (L3 == 31) carryn = 0;
    carryn += carry2;

    if (lane == L3) {
        unsigned b, ab;
        if (carryn + highc >= target) { b = (unsigned)(bbase + 2 * L3 + 1); ab = carryn; }
        else                          { b = (unsigned)(bbase + 2 * L3);     ab = carryn + highc; }
        *s_b = b; *s_above = ab;
    }
}

__device__ unsigned radix_threshold(unsigned* hist, unsigned* s1, unsigned hi, unsigned target,
                                    volatile unsigned* s_b, volatile unsigned* s_above,
                                    volatile int* s_all)
{
    const int tid = threadIdx.x;
    // vectorized zero: 32768 u32 = 8192 uint4
    for (int i = tid; i < 8192; i += T) ((uint4*)hist)[i] = make_uint4(0, 0, 0, 0);
    __syncthreads();
    for (int i = tid; i < N_ANCH; i += T) {
        unsigned bits = __float_as_uint(g_nscore[i]);
        if (bits <= hi) {
            unsigned b = bits >> 16;
            atomicAdd(&hist[b >> 1], 1u << ((b & 1) * 16));
        }
    }
    __syncthreads();
    {
        unsigned s = 0;
        #pragma unroll 8
        for (int q = 0; q < 32; q++) { unsigned w = hist[tid * 32 + q]; s += (w & 0xFFFFu) + (w >> 16); }
        s1[tid] = s;
    }
    __syncthreads();
    if (tid < 32) warp_select(hist, s1, target, s_b, s_above, s_all);
    __syncthreads();

    unsigned lo;
    if (*s_all) {
        lo = 0u;
    } else {
        unsigned b1  = *s_b;
        unsigned chi = *s_above;
        __syncthreads();
        for (int i = tid; i < 8192; i += T) ((uint4*)hist)[i] = make_uint4(0, 0, 0, 0);
        __syncthreads();
        for (int i = tid; i < N_ANCH; i += T) {
            unsigned bits = __float_as_uint(g_nscore[i]);
            if (bits <= hi && (bits >> 16) == b1) {
                unsigned b = bits & 0xFFFFu;
                atomicAdd(&hist[b >> 1], 1u << ((b & 1) * 16));
            }
        }
        __syncthreads();
        {
            unsigned s = 0;
            #pragma unroll 8
            for (int q = 0; q < 32; q++) { unsigned w = hist[tid * 32 + q]; s += (w & 0xFFFFu) + (w >> 16); }
            s1[tid] = s;
        }
        __syncthreads();
        if (tid < 32) warp_select(hist, s1, target - chi, s_b, s_above, s_all);
        __syncthreads();
        lo = (*s_all) ? (b1 << 16) : ((b1 << 16) | *s_b);
    }
    __syncthreads();
    return lo;
}

// collect bits in [lo,hi] into keys, sort descending; returns S (count).
// fast path: rank-sort (keys unique -> ranks are a permutation) when S <= T.
__device__ int collect_sort(unsigned long long* keys, unsigned lo, unsigned hi,
                            volatile unsigned* s_cnt)
{
    const int tid = threadIdx.x;
    if (tid == 0) *s_cnt = 0;
    __syncthreads();
    for (int i = tid; i < N_ANCH; i += T) {
        unsigned bits = __float_as_uint(g_nscore[i]);
        if (bits >= lo && bits <= hi) {
            unsigned p = atomicAdd((unsigned*)s_cnt, 1u);
            if (p < KEYCAP)
                keys[p] = ((unsigned long long)bits << 32) | (0xFFFFFFFFu - (unsigned)i);
        }
    }
    __syncthreads();
    int S = min((int)*s_cnt, KEYCAP);

    if (S <= T) {
        unsigned long long mykey = (tid < S) ? keys[tid] : 0ull;
        int rank = 0;
        if (tid < S) {
            for (int j = 0; j < S; j++) rank += (keys[j] > mykey) ? 1 : 0;
        }
        __syncthreads();
        if (tid < S) keys[rank] = mykey;
        __syncthreads();
    } else {
        int nsort = 1024;
        while (nsort < S) nsort <<= 1;
        for (int i = tid; i < nsort; i += T) if (i >= S) keys[i] = 0ull;
        __syncthreads();
        for (int k = 2; k <= nsort; k <<= 1) {
            for (int j = k >> 1; j > 0; j >>= 1) {
                for (int i = tid; i < nsort; i += T) {
                    int ixj = i ^ j;
                    if (ixj > i) {
                        unsigned long long a = keys[i], b = keys[ixj];
                        bool up = ((i & k) == 0);
                        if (up ? (a < b) : (a > b)) { keys[i] = b; keys[ixj] = a; }
                    }
                }
                __syncthreads();
            }
        }
    }
    return S;
}

// general (slow-path) chunk processor — only used beyond the first 512 candidates
__device__ int nms_chunk(int cn, int kept, bool build_mat,
                         float4* cbox, float* carea, unsigned* sprev, unsigned* cidx,
                         unsigned* mat, float4* kbox, float* karea, volatile int* s_kept)
{
    const int tid = threadIdx.x;
    const int lane = tid & 31;

    if (kept == 0) {
        for (int c = tid; c < cn; c += T) sprev[c] = 0;
    } else {
        for (int c = tid; c < cn; c += T) {
            float4 b = cbox[c]; float ba = carea[c];
            unsigned f = 0;
            for (int q = 0; q < kept; q++)
                if (iou_sup(kbox[q], karea[q], b, ba)) { f = 1; break; }
            sprev[c] = f;
        }
    }

    if (build_mat) {
        for (int iw = tid; iw < CH * 16; iw += T) {
            int i = iw & (CH - 1);
            int w = iw >> 9;
            int j0 = w << 5;
            if (i < cn && j0 < i) {
                float4 bi = cbox[i]; float ai = carea[i];
                int jmax = min(i, j0 + 32);
                unsigned word = 0;
                for (int j = j0; j < jmax; j++)
                    if (iou_sup(cbox[j], carea[j], bi, ai)) word |= 1u << (j - j0);
                mat[w * MAT_STRIDE + i] = word;
            } else if (i < cn) {
                mat[w * MAT_STRIDE + i] = 0u;
            }
        }
    }
    __syncthreads();

    if (tid < 32) {
        unsigned km = 0;
        int kp = kept;
        unsigned row = (lane < 16 && cn > 0) ? mat[lane * MAT_STRIDE] : 0u;
        for (int i = 0; i < cn && kp < PAD; i++) {
            unsigned nrow = (lane < 16 && i + 1 < cn) ? mat[lane * MAT_STRIDE + i + 1] : 0u;
            unsigned sp = sprev[i];
            bool clash = __any_sync(0xffffffffu, (row & km) != 0u) || (sp != 0u);
            if (!clash) {
                if (lane == 0) {
                    g_idx[kp]   = (int)cidx[i];
                    g_valid[kp] = 1.0f;
                    kbox[kp]    = cbox[i];
                    karea[kp]   = carea[i];
                }
                if (lane == (i >> 5)) km |= 1u << (i & 31);
                kp++;
            }
            row = nrow;
        }
        if (lane == 0) *s_kept = kp;
    }
    __syncthreads();
    return *s_kept;
}

// ---------------- kernel 2a: radix select + sort top batch (1 block) ----------------
__global__ __launch_bounds__(T, 1) void k_select()
{
    extern __shared__ char sm[];
    unsigned*           hist = (unsigned*)(sm);
    unsigned long long* keys = (unsigned long long*)(sm + OFF_KEYS);
    unsigned*           s1   = (unsigned*)(sm + OFF_S1);
    volatile unsigned*  s_cnt   = (volatile unsigned*)(sm + OFF_SCAL);
    volatile unsigned*  s_b     = (volatile unsigned*)(sm + OFF_SCAL + 8);
    volatile unsigned*  s_above = (volatile unsigned*)(sm + OFF_SCAL + 12);
    volatile int*       s_all   = (volatile int*)(sm + OFF_SCAL + 16);

    const int tid = threadIdx.x;

    unsigned lo = radix_threshold(hist, s1, 0xFFFFFFFFu, TARGET, s_b, s_above, s_all);
    int S = collect_sort(keys, lo, 0xFFFFFFFFu, s_cnt);

    for (int i = tid; i < S; i += T) g_skeys[i] = keys[i];
    for (int i = tid; i < 16 * 512; i += T) g_mat[i] = 0u;
    if (tid == 0) { g_S = S; g_lo = lo; }
}

// ---------------- kernel 2b: suppression bitmatrix on the full chip ----------------
__global__ void k_matrix()
{
    int id = blockIdx.x * blockDim.x + threadIdx.x;   // 8192 threads: cell (i, w)
    int i = id & 511;
    int w = id >> 9;
    int cn = min(g_S, CH);
    if (i >= cn) return;
    int j0 = w << 5;
    if (j0 >= i) return;

    unsigned idx_i = 0xFFFFFFFFu - (unsigned)g_skeys[i];
    float4 bi = g_pbox[idx_i];
    float  ai = (bi.z - bi.x + 1.0f) * (bi.w - bi.y + 1.0f);

    int jmax = min(i, j0 + 32);
    unsigned word = 0;
    for (int j = j0; j < jmax; j++) {
        unsigned idx_j = 0xFFFFFFFFu - (unsigned)g_skeys[j];
        float4 bj = g_pbox[idx_j];
        float  aj = (bj.z - bj.x + 1.0f) * (bj.w - bj.y + 1.0f);
        if (iou_sup(bj, aj, bi, ai)) word |= 1u << (j - j0);
    }
    g_mat[w * 512 + i] = word;
}

// ---------------- kernel 2c: sparse group-wise resolve + general fallback ----------------
__global__ __launch_bounds__(T, 1) void k_resolve()
{
    extern __shared__ char sm[];
    unsigned*           hist  = (unsigned*)(sm);
    float4*             cbox  = (float4*)(sm);
    float*              carea = (float*)(sm + 8192);
    unsigned*           sprev = (unsigned*)(sm + 10240);
    unsigned*           cidx  = (unsigned*)(sm + 12288);
    unsigned*           mat   = (unsigned*)(sm + 14336);
    unsigned*           smat  = (unsigned*)(sm + 47360);   // [16][512]
    unsigned*           scidx = (unsigned*)(sm + 80128);   // [512]
    unsigned long long* keys  = (unsigned long long*)(sm + OFF_KEYS);
    unsigned*           s1    = (unsigned*)(sm + OFF_S1);
    float4*             kbox  = (float4*)(sm + OFF_KBOX);
    float*              karea = (float*)(sm + OFF_KAREA);
    volatile unsigned*  s_cnt   = (volatile unsigned*)(sm + OFF_SCAL);
    volatile int*       s_kept  = (volatile int*)(sm + OFF_SCAL + 4);
    volatile unsigned*  s_b     = (volatile unsigned*)(sm + OFF_SCAL + 8);
    volatile unsigned*  s_above = (volatile unsigned*)(sm + OFF_SCAL + 12);
    volatile int*       s_all   = (volatile int*)(sm + OFF_SCAL + 16);

    const int tid = threadIdx.x;
    const int lane = tid & 31;

    int S = g_S;
    int cn0 = min(S, CH);

    // preload matrix (vectorized) + candidate indices (all warps)
    for (int i = tid; i < 2048; i += T) ((uint4*)smat)[i] = ((const uint4*)g_mat)[i];
    for (int i = tid; i < cn0; i += T) scidx[i] = 0xFFFFFFFFu - (unsigned)g_skeys[i];
    if (tid == 0) *s_kept = 0;
    __syncthreads();

    // ---- sparse resolve of first chunk: warp 0, 16 group-steps ----
    if (tid < 32) {
        unsigned km[16];            // kept masks per group (warp-uniform values)
        #pragma unroll
        for (int g = 0; g < 16; g++) km[g] = 0u;
        int kp = 0;

        #pragma unroll
        for (int g = 0; g < 16; g++) {
            if (kp >= PAD) break;                          // uniform
            int i = g * 32 + lane;
            bool active = i < cn0;
            unsigned r = active ? smat[g * 512 + i] : 0u;  // intra-group suppressors (j<i)
            unsigned clash = 0;
            #pragma unroll
            for (int w = 0; w < 16; w++) {
                if (w >= g) break;
                clash |= (active ? smat[w * 512 + i] : 0u) & km[w];
            }
            unsigned myidx = active ? scidx[i] : 0u;

            unsigned activeM  = __ballot_sync(0xffffffffu, active);
            unsigned suspects = __ballot_sync(0xffffffffu, active && ((r != 0u) || (clash != 0u)));

            unsigned kmg;
            if (suspects == 0u) {
                kmg = activeM;                              // everyone kept
            } else {
                kmg = activeM & ~suspects;                  // no-suppressor lanes kept for sure
                unsigned rem = suspects;
                while (rem) {                               // ~1-3 iterations typical
                    int t = __ffs(rem) - 1; rem &= rem - 1;
                    unsigned rt = __shfl_sync(0xffffffffu, r, t);
                    unsigned ct = __shfl_sync(0xffffffffu, clash, t);
                    // rt only contains bits j<t, so higher kept bits in kmg are harmless
                    if (ct == 0u && (rt & kmg) == 0u) kmg |= 1u << t;
                }
            }

            // PAD truncation + parallel output (ranks = prefix popcount)
            int allowed = PAD - kp;
            int cnt = __popc(kmg);
            int rank = __popc(kmg & ((1u << lane) - 1u));
            bool mykeep = ((kmg >> lane) & 1u) && (rank < allowed);
            if (mykeep) {
                g_idx[kp + rank]   = (int)myidx;
                g_valid[kp + rank] = 1.0f;
            }
            km[g] = __ballot_sync(0xffffffffu, mykeep);
            kp += min(cnt, allowed);
        }
        if (lane == 0) *s_kept = kp;
    }
    __syncthreads();
    int kept = *s_kept;

    // ---- general fallback (rare): more chunks in batch / further radix rounds ----
    if (kept < PAD && (S > CH || g_lo > 0)) {
        for (int q = tid; q < kept; q += T) {
            float4 b = g_pbox[g_idx[q]];
            kbox[q] = b;
            karea[q] = (b.z - b.x + 1.0f) * (b.w - b.y + 1.0f);
        }
        __syncthreads();

        for (int base = CH; base < S && kept < PAD; base += CH) {
            int cn = min(CH, S - base);
            for (int c = tid; c < cn; c += T) {
                unsigned idx = 0xFFFFFFFFu - (unsigned)g_skeys[base + c];
                cidx[c] = idx;
                float4 b = g_pbox[idx];
                cbox[c] = b;
                carea[c] = (b.z - b.x + 1.0f) * (b.w - b.y + 1.0f);
            }
            __syncthreads();
            kept = nms_chunk(cn, kept, true, cbox, carea, sprev, cidx, mat,
                             kbox, karea, s_kept);
        }

        if (kept < PAD && g_lo > 0) {
            unsigned hi = g_lo - 1u;
            while (kept < PAD) {
                unsigned lo = radix_threshold(hist, s1, hi, TARGET, s_b, s_above, s_all);
                int Sb = collect_sort(keys, lo, hi, s_cnt);
                for (int base = 0; base < Sb && kept < PAD; base += CH) {
                    int cn = min(CH, Sb - base);
                    for (int c = tid; c < cn; c += T) {
                        unsigned idx = 0xFFFFFFFFu - (unsigned)keys[base + c];
                        cidx[c] = idx;
                        float4 b = g_pbox[idx];
                        cbox[c] = b;
                        carea[c] = (b.z - b.x + 1.0f) * (b.w - b.y + 1.0f);
                    }
                    __syncthreads();
                    kept = nms_chunk(cn, kept, true, cbox, carea, sprev, cidx, mat,
                                     kbox, karea, s_kept);
                }
                if (lo == 0u) break;
                hi = lo - 1u;
                __syncthreads();
            }
        }
    }

    for (int r = kept + tid; r < PAD; r += T) { g_idx[r] = 0; g_valid[r] = 0.0f; }
}

// ---------------- kernel 3: gather (block-per-detection for masks) ----------------
#define OFF_SC  (PAD * 4)
#define OFF_MK  (OFF_SC + PAD * N_CLS)
#define PER_F4  (MASK_SZ / 4)                  // 3969
#define SMALL_BLOCKS ((OFF_MK + 255) / 256)    // 100

__global__ void k_gather(const float* __restrict__ scores,
                         const float* __restrict__ masks,
                         float* __restrict__ out)
{
    int b = blockIdx.x;
    if (b < PAD) {
        // masks for detection b
        int idx = g_idx[b];
        float s = g_valid[b];
        const float4* src = (const float4*)(masks + (size_t)idx * MASK_SZ);
        float4* dst = (float4*)(out + OFF_MK) + (size_t)b * PER_F4;
        for (int m = threadIdx.x; m < PER_F4; m += 256) {
            float4 v = src[m];
            v.x *= s; v.y *= s; v.z *= s; v.w *= s;
            dst[m] = v;
        }
    } else {
        int e = (b - PAD) * 256 + threadIdx.x;
        if (e >= OFF_MK) return;
        if (e < OFF_SC) {
            int k = e >> 2, c = e & 3;
            const float* bp = (const float*)&g_pbox[g_idx[k]];
            out[e] = bp[c] * g_valid[k];
        } else {
            int r = e - OFF_SC;
            int k = r / N_CLS, c = r - k * N_CLS;
            out[e] = scores[(size_t)g_idx[k] * N_CLS + c] * g_valid[k];
        }
    }
}

// ---------------- launch ----------------
extern "C" void kernel_launch(void* const* d_in, const int* in_sizes, int n_in,
                              void* d_out, int out_size)
{
    const float* meta   = (const float*)d_in[0];
    const float* deltas = (const float*)d_in[1];
    const float* props  = (const float*)d_in[2];
    const float* scores = (const float*)d_in[3];
    const float* masks  = (const float*)d_in[4];
    float* out = (float*)d_out;

    static bool attr_done = false;
    if (!attr_done) {
        cudaFuncSetAttribute(k_select,  cudaFuncAttributeMaxDynamicSharedMemorySize, SMEM_TOTAL);
        cudaFuncSetAttribute(k_resolve, cudaFuncAttributeMaxDynamicSharedMemorySize, SMEM_TOTAL);
        attr_done = true;
    }

    k_decode<<<(N_ANCH + 3) / 4, 128>>>(meta, deltas, props, scores);
    k_select<<<1, T, SMEM_TOTAL>>>();
    k_matrix<<<32, 256>>>();
    k_resolve<<<1, T, SMEM_TOTAL>>>();
    k_gather<<<PAD + SMALL_BLOCKS, 256>>>(scores, masks, out);
}

// round 8
// speedup vs baseline: 16.1897x; 1.5270x over previous
#include <cuda_runtime.h>
#include <cuda_bf16.h>
#include <math.h>

#define N_ANCH 6000
#define N_CLS  81
#define PAD    300
#define MASK_SZ (14*14*81)   // 15876
#define NMS_THRESH 0.5f
#define T      1024
#define GRID   120
#define NW     (GRID * 32)
#define TARGET 512u
#define KEYCAP 8192
#define CH     512
#define MAT_STRIDE 516
#define NPAIR  (512 * 511 / 2)   // 130816

// ---- dynamic smem layout (bytes) ----
#define OFF_KEYS  131072   // u64[8192]  (65536) -> 196608
#define OFF_S1    196608   // u32[1024]  (4096)  -> 200704
#define OFF_KBOX  200704   // float4[300](4800)  -> 205504
#define OFF_KAREA 205504   // f32[300]   (1200)  -> 206704
#define OFF_SCAL  206704
#define SMEM_TOTAL 206848
// region A aliases:
//   hist u32[32768]@0 (131072)  -- select/fallback
//   cbox f4[512]@0 | carea f32[512]@8192 | sprev u32[512]@10240
//   cidx u32[512]@12288 | mat u32[16*516]@14336 (33024)
//   smat u32[16*512]@47360 (32768) | scidx u32[512]@80128 (2048)

// ---------------- scratch (device globals, no allocation) ----------------
__device__ float4 g_pbox[N_ANCH];
__device__ float  g_nscore[N_ANCH];
__device__ unsigned long long g_skeys[KEYCAP];
__device__ int      g_S;
__device__ unsigned g_lo;
__device__ unsigned g_mat[16 * 512];
__device__ int    g_idx[PAD];
__device__ float  g_valid[PAD];
// grid-sync counters (reset to 0 by block 0 at end of every run)
__device__ int c_dec, f_sel, c_mat, f_res, c_fin;

__device__ __forceinline__ void spin_ge(int* c, int v)
{
    if (threadIdx.x == 0) {
        while (*(volatile int*)c < v) __nanosleep(64);
        __threadfence();
    }
    __syncthreads();
}
__device__ __forceinline__ void signal(int* c)
{
    __syncthreads();
    if (threadIdx.x == 0) { __threadfence(); atomicAdd(c, 1); }
}

__device__ __forceinline__ bool iou_sup(float4 a, float aa, float4 b, float ba)
{
    float xx1 = fmaxf(a.x, b.x);
    float yy1 = fmaxf(a.y, b.y);
    float xx2 = fminf(a.z, b.z);
    float yy2 = fminf(a.w, b.w);
    float iw = fmaxf(xx2 - xx1 + 1.0f, 0.0f);
    float ih = fmaxf(yy2 - yy1 + 1.0f, 0.0f);
    float inter = iw * ih;
    return inter / (aa + ba - inter) > NMS_THRESH;
}

// warp-0 hierarchical suffix search over 65536-bucket histogram.
__device__ __forceinline__ void warp_select(const unsigned* hist, const unsigned* s1,
                                            unsigned target,
                                            volatile unsigned* s_b,
                                            volatile unsigned* s_above,
                                            volatile int* s_all)
{
    int lane = threadIdx.x;

    unsigned s2 = 0;
    #pragma unroll 8
    for (int q = 0; q < 32; q++) s2 += s1[lane * 32 + q];
    unsigned incl = s2;
    #pragma unroll
    for (int off = 1; off < 32; off <<= 1) {
        unsigned v = __shfl_down_sync(0xffffffffu, incl, off);
        if (lane + off < 32) incl += v;
    }
    unsigned total = __shfl_sync(0xffffffffu, incl, 0);
    if (total < target) { if (lane == 0) *s_all = 1; return; }
    if (lane == 0) *s_all = 0;

    unsigned bal = __ballot_sync(0xffffffffu, incl >= target);
    int L1 = 31 - __clz(bal);
    unsigned carry1 = __shfl_sync(0xffffffffu, incl, (L1 + 1) & 31);
    if (L1 == 31) carry1 = 0;

    incl = s1[L1 * 32 + lane];
    #pragma unroll
    for (int off = 1; off < 32; off <<= 1) {
        unsigned v = __shfl_down_sync(0xffffffffu, incl, off);
        if (lane + off < 32) incl += v;
    }
    bal = __ballot_sync(0xffffffffu, carry1 + incl >= target);
    int L2 = 31 - __clz(bal);
    unsigned carry2 = __shfl_sync(0xffffffffu, incl, (L2 + 1) & 31);
    if (L2 == 31) carry2 = 0;
    carry2 += carry1;

    int bbase = (L1 * 32 + L2) * 64;
    unsigned w = hist[(bbase >> 1) + lane];
    unsigned lowc = w & 0xFFFFu, highc = w >> 16;
    incl = lowc + highc;
    #pragma unroll
    for (int off = 1; off < 32; off <<= 1) {
        unsigned v = __shfl_down_sync(0xffffffffu, incl, off);
        if (lane + off < 32) incl += v;
    }
    bal = __ballot_sync(0xffffffffu, carry2 + incl >= target);
    int L3 = 31 - __clz(bal);
    unsigned carryn = __shfl_sync(0xffffffffu, incl, (L3 + 1) & 31);
    if (L3 == 31) carryn = 0;
    carryn += carry2;

    if (lane == L3) {
        unsigned b, ab;
        if (carryn + highc >= target) { b = (unsigned)(bbase + 2 * L3 + 1); ab = carryn; }
        else                          { b = (unsigned)(bbase + 2 * L3);     ab = carryn + highc; }
        *s_b = b; *s_above = ab;
    }
}

__device__ unsigned radix_threshold(unsigned* hist, unsigned* s1, unsigned hi, unsigned target,
                                    volatile unsigned* s_b, volatile unsigned* s_above,
                                    volatile int* s_all)
{
    const int tid = threadIdx.x;
    for (int i = tid; i < 8192; i += T) ((uint4*)hist)[i] = make_uint4(0, 0, 0, 0);
    __syncthreads();
    for (int i = tid; i < N_ANCH; i += T) {
        unsigned bits = __float_as_uint(g_nscore[i]);
        if (bits <= hi) {
            unsigned b = bits >> 16;
            atomicAdd(&hist[b >> 1], 1u << ((b & 1) * 16));
        }
    }
    __syncthreads();
    {
        unsigned s = 0;
        #pragma unroll 8
        for (int q = 0; q < 32; q++) { unsigned w = hist[tid * 32 + q]; s += (w & 0xFFFFu) + (w >> 16); }
        s1[tid] = s;
    }
    __syncthreads();
    if (tid < 32) warp_select(hist, s1, target, s_b, s_above, s_all);
    __syncthreads();

    unsigned lo;
    if (*s_all) {
        lo = 0u;
    } else {
        unsigned b1  = *s_b;
        unsigned chi = *s_above;
        __syncthreads();
        for (int i = tid; i < 8192; i += T) ((uint4*)hist)[i] = make_uint4(0, 0, 0, 0);
        __syncthreads();
        for (int i = tid; i < N_ANCH; i += T) {
            unsigned bits = __float_as_uint(g_nscore[i]);
            if (bits <= hi && (bits >> 16) == b1) {
                unsigned b = bits & 0xFFFFu;
                atomicAdd(&hist[b >> 1], 1u << ((b & 1) * 16));
            }
        }
        __syncthreads();
        {
            unsigned s = 0;
            #pragma unroll 8
            for (int q = 0; q < 32; q++) { unsigned w = hist[tid * 32 + q]; s += (w & 0xFFFFu) + (w >> 16); }
            s1[tid] = s;
        }
        __syncthreads();
        if (tid < 32) warp_select(hist, s1, target - chi, s_b, s_above, s_all);
        __syncthreads();
        lo = (*s_all) ? (b1 << 16) : ((b1 << 16) | *s_b);
    }
    __syncthreads();
    return lo;
}

__device__ int collect_sort(unsigned long long* keys, unsigned lo, unsigned hi,
                            volatile unsigned* s_cnt)
{
    const int tid = threadIdx.x;
    if (tid == 0) *s_cnt = 0;
    __syncthreads();
    for (int i = tid; i < N_ANCH; i += T) {
        unsigned bits = __float_as_uint(g_nscore[i]);
        if (bits >= lo && bits <= hi) {
            unsigned p = atomicAdd((unsigned*)s_cnt, 1u);
            if (p < KEYCAP)
                keys[p] = ((unsigned long long)bits << 32) | (0xFFFFFFFFu - (unsigned)i);
        }
    }
    __syncthreads();
    int S = min((int)*s_cnt, KEYCAP);

    if (S <= T) {
        unsigned long long mykey = (tid < S) ? keys[tid] : 0ull;
        int rank = 0;
        if (tid < S) {
            for (int j = 0; j < S; j++) rank += (keys[j] > mykey) ? 1 : 0;
        }
        __syncthreads();
        if (tid < S) keys[rank] = mykey;
        __syncthreads();
    } else {
        int nsort = 1024;
        while (nsort < S) nsort <<= 1;
        for (int i = tid; i < nsort; i += T) if (i >= S) keys[i] = 0ull;
        __syncthreads();
        for (int k = 2; k <= nsort; k <<= 1) {
            for (int j = k >> 1; j > 0; j >>= 1) {
                for (int i = tid; i < nsort; i += T) {
                    int ixj = i ^ j;
                    if (ixj > i) {
                        unsigned long long a = keys[i], b = keys[ixj];
                        bool up = ((i & k) == 0);
                        if (up ? (a < b) : (a > b)) { keys[i] = b; keys[ixj] = a; }
                    }
                }
                __syncthreads();
            }
        }
    }
    return S;
}

// general (slow-path) chunk processor — only for candidates beyond the first 512
__device__ int nms_chunk(int cn, int kept, bool build_mat,
                         float4* cbox, float* carea, unsigned* sprev, unsigned* cidx,
                         unsigned* mat, float4* kbox, float* karea, volatile int* s_kept)
{
    const int tid = threadIdx.x;
    const int lane = tid & 31;

    if (kept == 0) {
        for (int c = tid; c < cn; c += T) sprev[c] = 0;
    } else {
        for (int c = tid; c < cn; c += T) {
            float4 b = cbox[c]; float ba = carea[c];
            unsigned f = 0;
            for (int q = 0; q < kept; q++)
                if (iou_sup(kbox[q], karea[q], b, ba)) { f = 1; break; }
            sprev[c] = f;
        }
    }

    if (build_mat) {
        for (int iw = tid; iw < CH * 16; iw += T) {
            int i = iw & (CH - 1);
            int w = iw >> 9;
            int j0 = w << 5;
            if (i < cn && j0 < i) {
                float4 bi = cbox[i]; float ai = carea[i];
                int jmax = min(i, j0 + 32);
                unsigned word = 0;
                for (int j = j0; j < jmax; j++)
                    if (iou_sup(cbox[j], carea[j], bi, ai)) word |= 1u << (j - j0);
                mat[w * MAT_STRIDE + i] = word;
            } else if (i < cn) {
                mat[w * MAT_STRIDE + i] = 0u;
            }
        }
    }
    __syncthreads();

    if (tid < 32) {
        unsigned km = 0;
        int kp = kept;
        unsigned row = (lane < 16 && cn > 0) ? mat[lane * MAT_STRIDE] : 0u;
        for (int i = 0; i < cn && kp < PAD; i++) {
            unsigned nrow = (lane < 16 && i + 1 < cn) ? mat[lane * MAT_STRIDE + i + 1] : 0u;
            unsigned sp = sprev[i];
            bool clash = __any_sync(0xffffffffu, (row & km) != 0u) || (sp != 0u);
            if (!clash) {
                if (lane == 0) {
                    g_idx[kp]   = (int)cidx[i];
                    g_valid[kp] = 1.0f;
                    kbox[kp]    = cbox[i];
                    karea[kp]   = carea[i];
                }
                if (lane == (i >> 5)) km |= 1u << (i & 31);
                kp++;
            }
            row = nrow;
        }
        if (lane == 0) *s_kept = kp;
    }
    __syncthreads();
    return *s_kept;
}

// ---------------- output layout ----------------
#define OFF_SC  (PAD * 4)
#define OFF_MK  (OFF_SC + PAD * N_CLS)
#define PER_F4  (MASK_SZ / 4)   // 3969

// ---------------- THE mega-kernel: everything in one launch ----------------
__global__ __launch_bounds__(T, 1) void k_mega(
    const float* __restrict__ meta,
    const float* __restrict__ deltas,
    const float* __restrict__ props,
    const float* __restrict__ scores,
    const float* __restrict__ masks,
    float* __restrict__ out)
{
    extern __shared__ char sm[];
    unsigned*           hist  = (unsigned*)(sm);
    float4*             cbox  = (float4*)(sm);
    float*              carea = (float*)(sm + 8192);
    unsigned*           sprev = (unsigned*)(sm + 10240);
    unsigned*           cidx  = (unsigned*)(sm + 12288);
    unsigned*           mat   = (unsigned*)(sm + 14336);
    unsigned*           smat  = (unsigned*)(sm + 47360);   // [16][512]
    unsigned*           scidx = (unsigned*)(sm + 80128);   // [512]
    unsigned long long* keys  = (unsigned long long*)(sm + OFF_KEYS);
    unsigned*           s1    = (unsigned*)(sm + OFF_S1);
    float4*             kbox  = (float4*)(sm + OFF_KBOX);
    float*              karea = (float*)(sm + OFF_KAREA);
    volatile unsigned*  s_cnt   = (volatile unsigned*)(sm + OFF_SCAL);
    volatile int*       s_kept  = (volatile int*)(sm + OFF_SCAL + 4);
    volatile unsigned*  s_b     = (volatile unsigned*)(sm + OFF_SCAL + 8);
    volatile unsigned*  s_above = (volatile unsigned*)(sm + OFF_SCAL + 12);
    volatile int*       s_all   = (volatile int*)(sm + OFF_SCAL + 16);

    const int tid  = threadIdx.x;
    const int lane = tid & 31;
    const int bid  = blockIdx.x;
    const int gtid = bid * T + tid;

    // ================= phase 0: decode (all blocks, warp per anchor) =================
    {
        int gw = bid * 32 + (tid >> 5);
        for (int a = gw; a < N_ANCH; a += NW) {
            const float* srow = scores + (size_t)a * N_CLS;
            float bv = -INFINITY; int bc = 0;
            float ms = -INFINITY;
            for (int c = lane; c < N_CLS; c += 32) {
                float v = srow[c];
                if (v > bv) { bv = v; bc = c; }
                if (c >= 1) ms = fmaxf(ms, v);
            }
            #pragma unroll
            for (int off = 16; off; off >>= 1) {
                float ov  = __shfl_down_sync(0xffffffffu, bv, off);
                int   oc  = __shfl_down_sync(0xffffffffu, bc, off);
                float oms = __shfl_down_sync(0xffffffffu, ms, off);
                if (ov > bv || (ov == bv && oc < bc)) { bv = ov; bc = oc; }
                ms = fmaxf(ms, oms);
            }
            if (lane == 0) {
                float H = meta[0], W = meta[1], scale = meta[2];
                const float* p = props + (size_t)a * 4;
                float x1 = p[0] / scale, y1 = p[1] / scale;
                float x2 = p[2] / scale, y2 = p[3] / scale;
                float w  = x2 - x1 + 1.0f, h = y2 - y1 + 1.0f;
                float cx = x1 + 0.5f * w, cy = y1 + 0.5f * h;

                const float* d = deltas + (size_t)a * (4 * N_CLS) + bc * 4;
                float pcx = d[0] * w + cx;
                float pcy = d[1] * h + cy;
                float pw  = expf(d[2]) * w;
                float ph  = expf(d[3]) * h;

                float px1 = pcx - 0.5f * pw, py1 = pcy - 0.5f * ph;
                float px2 = pcx + 0.5f * pw, py2 = pcy + 0.5f * ph;
                px1 = fminf(fmaxf(px1, 0.0f), W - 1.0f);
                py1 = fminf(fmaxf(py1, 0.0f), H - 1.0f);
                px2 = fminf(fmaxf(px2, 0.0f), W - 1.0f);
                py2 = fminf(fmaxf(py2, 0.0f), H - 1.0f);

                g_pbox[a] = make_float4(px1, py1, px2, py2);
                g_nscore[a] = ms;
            }
        }
        // zero the global bitmatrix (visible to atomicOr writers via the sync chain)
        for (int i = gtid; i < 16 * 512; i += GRID * T) g_mat[i] = 0u;
    }
    signal(&c_dec);

    // ================= phase 1: select (block 0 only) =================
    if (bid == 0) {
        spin_ge(&c_dec, GRID);
        unsigned lo = radix_threshold(hist, s1, 0xFFFFFFFFu, TARGET, s_b, s_above, s_all);
        int S = collect_sort(keys, lo, 0xFFFFFFFFu, s_cnt);
        for (int i = tid; i < S; i += T) g_skeys[i] = keys[i];
        __syncthreads();
        if (tid == 0) { g_S = S; g_lo = lo; __threadfence(); atomicExch(&f_sel, 1); }
        __syncthreads();
    }

    // ================= phase 2: bitmatrix as flat pairs (all blocks) =================
    spin_ge(&f_sel, 1);
    {
        int cn = min(g_S, CH);
        for (int p = gtid; p < NPAIR; p += GRID * T) {
            // p -> (i, j), j < i, lower triangular
            int i = (int)((1.0 + sqrt(1.0 + 8.0 * (double)p)) * 0.5);
            while (i * (i - 1) / 2 > p) i--;
            while ((i + 1) * i / 2 <= p) i++;
            int j = p - i * (i - 1) / 2;
            if (i >= cn) continue;

            unsigned idx_i = 0xFFFFFFFFu - (unsigned)g_skeys[i];
            unsigned idx_j = 0xFFFFFFFFu - (unsigned)g_skeys[j];
            float4 bi = g_pbox[idx_i];
            float4 bj = g_pbox[idx_j];
            float  ai = (bi.z - bi.x + 1.0f) * (bi.w - bi.y + 1.0f);
            float  aj = (bj.z - bj.x + 1.0f) * (bj.w - bj.y + 1.0f);
            if (iou_sup(bj, aj, bi, ai))
                atomicOr(&g_mat[(j >> 5) * 512 + i], 1u << (j & 31));
        }
    }
    signal(&c_mat);

    // ================= phase 3: resolve (block 0 only) =================
    if (bid == 0) {
        spin_ge(&c_mat, GRID);

        int S = g_S;
        int cn0 = min(S, CH);

        for (int i = tid; i < 2048; i += T) ((uint4*)smat)[i] = ((const uint4*)g_mat)[i];
        for (int i = tid; i < cn0; i += T) scidx[i] = 0xFFFFFFFFu - (unsigned)g_skeys[i];
        if (tid == 0) *s_kept = 0;
        __syncthreads();

        // sparse group-wise resolve by warp 0
        if (tid < 32) {
            unsigned km[16];
            #pragma unroll
            for (int g = 0; g < 16; g++) km[g] = 0u;
            int kp = 0;

            #pragma unroll
            for (int g = 0; g < 16; g++) {
                if (kp >= PAD) break;
                int i = g * 32 + lane;
                bool active = i < cn0;
                unsigned r = active ? smat[g * 512 + i] : 0u;
                unsigned clash = 0;
                #pragma unroll
                for (int w = 0; w < 16; w++) {
                    if (w >= g) break;
                    clash |= (active ? smat[w * 512 + i] : 0u) & km[w];
                }
                unsigned myidx = active ? scidx[i] : 0u;

                unsigned activeM  = __ballot_sync(0xffffffffu, active);
                unsigned suspects = __ballot_sync(0xffffffffu, active && ((r != 0u) || (clash != 0u)));

                unsigned kmg;
                if (suspects == 0u) {
                    kmg = activeM;
                } else {
                    kmg = activeM & ~suspects;
                    unsigned rem = suspects;
                    while (rem) {
                        int t = __ffs(rem) - 1; rem &= rem - 1;
                        unsigned rt = __shfl_sync(0xffffffffu, r, t);
                        unsigned ct = __shfl_sync(0xffffffffu, clash, t);
                        if (ct == 0u && (rt & kmg) == 0u) kmg |= 1u << t;
                    }
                }

                int allowed = PAD - kp;
                int cnt = __popc(kmg);
                int rank = __popc(kmg & ((1u << lane) - 1u));
                bool mykeep = ((kmg >> lane) & 1u) && (rank < allowed);
                if (mykeep) {
                    g_idx[kp + rank]   = (int)myidx;
                    g_valid[kp + rank] = 1.0f;
                }
                km[g] = __ballot_sync(0xffffffffu, mykeep);
                kp += min(cnt, allowed);
            }
            if (lane == 0) *s_kept = kp;
        }
        __syncthreads();
        int kept = *s_kept;

        // general fallback (rare): more chunks / further radix rounds
        if (kept < PAD && (S > CH || g_lo > 0)) {
            for (int q = tid; q < kept; q += T) {
                float4 b = g_pbox[g_idx[q]];
                kbox[q] = b;
                karea[q] = (b.z - b.x + 1.0f) * (b.w - b.y + 1.0f);
            }
            __syncthreads();

            for (int base = CH; base < S && kept < PAD; base += CH) {
                int cn = min(CH, S - base);
                for (int c = tid; c < cn; c += T) {
                    unsigned idx = 0xFFFFFFFFu - (unsigned)g_skeys[base + c];
                    cidx[c] = idx;
                    float4 b = g_pbox[idx];
                    cbox[c] = b;
                    carea[c] = (b.z - b.x + 1.0f) * (b.w - b.y + 1.0f);
                }
                __syncthreads();
                kept = nms_chunk(cn, kept, true, cbox, carea, sprev, cidx, mat,
                                 kbox, karea, s_kept);
            }

            if (kept < PAD && g_lo > 0) {
                unsigned hi = g_lo - 1u;
                while (kept < PAD) {
                    unsigned lo = radix_threshold(hist, s1, hi, TARGET, s_b, s_above, s_all);
                    int Sb = collect_sort(keys, lo, hi, s_cnt);
                    for (int base = 0; base < Sb && kept < PAD; base += CH) {
                        int cn = min(CH, Sb - base);
                        for (int c = tid; c < cn; c += T) {
                            unsigned idx = 0xFFFFFFFFu - (unsigned)keys[base + c];
                            cidx[c] = idx;
                            float4 b = g_pbox[idx];
                            cbox[c] = b;
                            carea[c] = (b.z - b.x + 1.0f) * (b.w - b.y + 1.0f);
                        }
                        __syncthreads();
                        kept = nms_chunk(cn, kept, true, cbox, carea, sprev, cidx, mat,
                                         kbox, karea, s_kept);
                    }
                    if (lo == 0u) break;
                    hi = lo - 1u;
                    __syncthreads();
                }
            }
        }

        for (int r = kept + tid; r < PAD; r += T) { g_idx[r] = 0; g_valid[r] = 0.0f; }
        __syncthreads();
        if (tid == 0) { __threadfence(); atomicExch(&f_res, 1); }
        __syncthreads();
    }

    // ================= phase 4: gather (all blocks) =================
    spin_ge(&f_res, 1);
    {
        // masks: detections striped over blocks
        for (int d = bid; d < PAD; d += GRID) {
            int idx = g_idx[d];
            float s = g_valid[d];
            const float4* src = (const float4*)(masks + (size_t)idx * MASK_SZ);
            float4* dst = (float4*)(out + OFF_MK) + (size_t)d * PER_F4;
            for (int m = tid; m < PER_F4; m += T) {
                float4 v = src[m];
                v.x *= s; v.y *= s; v.z *= s; v.w *= s;
                dst[m] = v;
            }
        }
        // boxes + scores: global thread stripe (single pass)
        if (gtid < OFF_MK) {
            int e = gtid;
            if (e < OFF_SC) {
                int k = e >> 2, c = e & 3;
                const float* bp = (const float*)&g_pbox[g_idx[k]];
                out[e] = bp[c] * g_valid[k];
            } else {
                int r = e - OFF_SC;
                int k = r / N_CLS, c = r - k * N_CLS;
                out[e] = scores[(size_t)g_idx[k] * N_CLS + c] * g_valid[k];
            }
        }
    }
    signal(&c_fin);

    // ================= phase 5: reset counters for next graph replay =================
    if (bid == 0) {
        if (tid == 0) {
            while (*(volatile int*)&c_fin < GRID) __nanosleep(64);
            c_dec = 0; f_sel = 0; c_mat = 0; f_res = 0; c_fin = 0;
            __threadfence();
        }
    }
}

// ---------------- launch ----------------
extern "C" void kernel_launch(void* const* d_in, const int* in_sizes, int n_in,
                              void* d_out, int out_size)
{
    const float* meta   = (const float*)d_in[0];
    const float* deltas = (const float*)d_in[1];
    const float* props  = (const float*)d_in[2];
    const float* scores = (const float*)d_in[3];
    const float* masks  = (const float*)d_in[4];
    float* out = (float*)d_out;

    static bool attr_done = false;
    if (!attr_done) {
        cudaFuncSetAttribute(k_mega, cudaFuncAttributeMaxDynamicSharedMemorySize, SMEM_TOTAL);
        attr_done = true;
    }

    k_mega<<<GRID, T, SMEM_TOTAL>>>(meta, deltas, props, scores, masks, out);
}

// round 9
// speedup vs baseline: 17.6093x; 1.0877x over previous
#include <cuda_runtime.h>
#include <cuda_bf16.h>
#include <math.h>

#define N_ANCH 6000
#define N_CLS  81
#define PAD    300
#define MASK_SZ (14*14*81)   // 15876
#define NMS_THRESH 0.5f
#define T      1024
#define GRID   120
#define NW     (GRID * 32)
#define TARGET 512u
#define KEYCAP 8192
#define CH     512
#define MAT_STRIDE 516
#define NPAIR  (512 * 511 / 2)   // 130816

// ---- dynamic smem layout (bytes) ----
#define OFF_KEYS  131072   // u64[8192]  (65536) -> 196608
#define OFF_S1    196608   // u32[1024]  (4096)  -> 200704
#define OFF_KBOX  200704   // float4[300](4800)  -> 205504
#define OFF_KAREA 205504   // f32[300]   (1200)  -> 206704
#define OFF_SCAL  206704
#define SMEM_TOTAL 206848
// region A aliases:
//   hist u32[32768]@0 (131072)  -- select/fallback
//   cbox f4[512]@0 | carea f32[512]@8192 | sprev u32[512]@10240
//   cidx u32[512]@12288 | mat u32[16*516]@14336 (33024)
//   smat u32[16*512]@47360 (32768) | scidx u32[512]@80128 (2048)

// ---------------- scratch (device globals, no allocation) ----------------
__device__ float  g_nscore[N_ANCH];
__device__ int    g_cls[N_ANCH];
__device__ unsigned long long g_skeys[KEYCAP];
__device__ float4 g_cbox[CH];      // decoded boxes of top candidates (sorted order)
__device__ float  g_carea[CH];
__device__ int      g_S;
__device__ unsigned g_lo;
__device__ unsigned g_mat[16 * 512];
__device__ int    g_idx[PAD];      // kept anchor indices
__device__ float  g_valid[PAD];
__device__ float4 g_obox[PAD];     // kept boxes (always finite)
// grid-sync counters (reset to 0 by block 0 at end of every run)
__device__ int c_dec, f_sel, c_mat, f_res, c_fin;

__device__ __forceinline__ void spin_ge(int* c, int v)
{
    if (threadIdx.x == 0) {
        while (*(volatile int*)c < v) __nanosleep(64);
        __threadfence();
    }
    __syncthreads();
}
__device__ __forceinline__ void signal(int* c)
{
    __syncthreads();
    if (threadIdx.x == 0) { __threadfence(); atomicAdd(c, 1); }
}

__device__ __forceinline__ bool iou_sup(float4 a, float aa, float4 b, float ba)
{
    float xx1 = fmaxf(a.x, b.x);
    float yy1 = fmaxf(a.y, b.y);
    float xx2 = fminf(a.z, b.z);
    float yy2 = fminf(a.w, b.w);
    float iw = fmaxf(xx2 - xx1 + 1.0f, 0.0f);
    float ih = fmaxf(yy2 - yy1 + 1.0f, 0.0f);
    float inter = iw * ih;
    return inter / (aa + ba - inter) > NMS_THRESH;
}

// exact same arithmetic as the original per-anchor decode
__device__ __forceinline__ float4 decode_box(int a,
    const float* __restrict__ meta,
    const float* __restrict__ deltas,
    const float* __restrict__ props)
{
    float H = meta[0], W = meta[1], scale = meta[2];
    const float* p = props + (size_t)a * 4;
    float x1 = p[0] / scale, y1 = p[1] / scale;
    float x2 = p[2] / scale, y2 = p[3] / scale;
    float w  = x2 - x1 + 1.0f, h = y2 - y1 + 1.0f;
    float cx = x1 + 0.5f * w, cy = y1 + 0.5f * h;

    int bc = g_cls[a];
    const float* d = deltas + (size_t)a * (4 * N_CLS) + bc * 4;
    float pcx = d[0] * w + cx;
    float pcy = d[1] * h + cy;
    float pw  = expf(d[2]) * w;
    float ph  = expf(d[3]) * h;

    float px1 = pcx - 0.5f * pw, py1 = pcy - 0.5f * ph;
    float px2 = pcx + 0.5f * pw, py2 = pcy + 0.5f * ph;
    px1 = fminf(fmaxf(px1, 0.0f), W - 1.0f);
    py1 = fminf(fmaxf(py1, 0.0f), H - 1.0f);
    px2 = fminf(fmaxf(px2, 0.0f), W - 1.0f);
    py2 = fminf(fmaxf(py2, 0.0f), H - 1.0f);
    return make_float4(px1, py1, px2, py2);
}

// warp-0 hierarchical suffix search over 65536-bucket histogram.
__device__ __forceinline__ void warp_select(const unsigned* hist, const unsigned* s1,
                                            unsigned target,
                                            volatile unsigned* s_b,
                                            volatile unsigned* s_above,
                                            volatile int* s_all)
{
    int lane = threadIdx.x;

    unsigned s2 = 0;
    #pragma unroll 8
    for (int q = 0; q < 32; q++) s2 += s1[lane * 32 + q];
    unsigned incl = s2;
    #pragma unroll
    for (int off = 1; off < 32; off <<= 1) {
        unsigned v = __shfl_down_sync(0xffffffffu, incl, off);
        if (lane + off < 32) incl += v;
    }
    unsigned total = __shfl_sync(0xffffffffu, incl, 0);
    if (total < target) { if (lane == 0) *s_all = 1; return; }
    if (lane == 0) *s_all = 0;

    unsigned bal = __ballot_sync(0xffffffffu, incl >= target);
    int L1 = 31 - __clz(bal);
    unsigned carry1 = __shfl_sync(0xffffffffu, incl, (L1 + 1) & 31);
    if (L1 == 31) carry1 = 0;

    incl = s1[L1 * 32 + lane];
    #pragma unroll
    for (int off = 1; off < 32; off <<= 1) {
        unsigned v = __shfl_down_sync(0xffffffffu, incl, off);
        if (lane + off < 32) incl += v;
    }
    bal = __ballot_sync(0xffffffffu, carry1 + incl >= target);
    int L2 = 31 - __clz(bal);
    unsigned carry2 = __shfl_sync(0xffffffffu, incl, (L2 + 1) & 31);
    if (L2 == 31) carry2 = 0;
    carry2 += carry1;

    int bbase = (L1 * 32 + L2) * 64;
    unsigned w = hist[(bbase >> 1) + lane];
    unsigned lowc = w & 0xFFFFu, highc = w >> 16;
    incl = lowc + highc;
    #pragma unroll
    for (int off = 1; off < 32; off <<= 1) {
        unsigned v = __shfl_down_sync(0xffffffffu, incl, off);
        if (lane + off < 32) incl += v;
    }
    bal = __ballot_sync(0xffffffffu, carry2 + incl >= target);
    int L3 = 31 - __clz(bal);
    unsigned carryn = __shfl_sync(0xffffffffu, incl, (L3 + 1) & 31);
    if (L3 == 31) carryn = 0;
    carryn += carry2;

    if (lane == L3) {
        unsigned b, ab;
        if (carryn + highc >= target) { b = (unsigned)(bbase + 2 * L3 + 1); ab = carryn; }
        else                          { b = (unsigned)(bbase + 2 * L3);     ab = carryn + highc; }
        *s_b = b; *s_above = ab;
    }
}

__device__ unsigned radix_threshold(unsigned* hist, unsigned* s1, unsigned hi, unsigned target,
                                    volatile unsigned* s_b, volatile unsigned* s_above,
                                    volatile int* s_all)
{
    const int tid = threadIdx.x;
    for (int i = tid; i < 8192; i += T) ((uint4*)hist)[i] = make_uint4(0, 0, 0, 0);
    __syncthreads();
    for (int i = tid; i < N_ANCH; i += T) {
        unsigned bits = __float_as_uint(g_nscore[i]);
        if (bits <= hi) {
            unsigned b = bits >> 16;
            atomicAdd(&hist[b >> 1], 1u << ((b & 1) * 16));
        }
    }
    __syncthreads();
    {
        unsigned s = 0;
        #pragma unroll 8
        for (int q = 0; q < 32; q++) { unsigned w = hist[tid * 32 + q]; s += (w & 0xFFFFu) + (w >> 16); }
        s1[tid] = s;
    }
    __syncthreads();
    if (tid < 32) warp_select(hist, s1, target, s_b, s_above, s_all);
    __syncthreads();

    unsigned lo;
    if (*s_all) {
        lo = 0u;
    } else {
        unsigned b1  = *s_b;
        unsigned chi = *s_above;
        __syncthreads();
        for (int i = tid; i < 8192; i += T) ((uint4*)hist)[i] = make_uint4(0, 0, 0, 0);
        __syncthreads();
        for (int i = tid; i < N_ANCH; i += T) {
            unsigned bits = __float_as_uint(g_nscore[i]);
            if (bits <= hi && (bits >> 16) == b1) {
                unsigned b = bits & 0xFFFFu;
                atomicAdd(&hist[b >> 1], 1u << ((b & 1) * 16));
            }
        }
        __syncthreads();
        {
            unsigned s = 0;
            #pragma unroll 8
            for (int q = 0; q < 32; q++) { unsigned w = hist[tid * 32 + q]; s += (w & 0xFFFFu) + (w >> 16); }
            s1[tid] = s;
        }
        __syncthreads();
        if (tid < 32) warp_select(hist, s1, target - chi, s_b, s_above, s_all);
        __syncthreads();
        lo = (*s_all) ? (b1 << 16) : ((b1 << 16) | *s_b);
    }
    __syncthreads();
    return lo;
}

__device__ int collect_sort(unsigned long long* keys, unsigned lo, unsigned hi,
                            volatile unsigned* s_cnt)
{
    const int tid = threadIdx.x;
    if (tid == 0) *s_cnt = 0;
    __syncthreads();
    for (int i = tid; i < N_ANCH; i += T) {
        unsigned bits = __float_as_uint(g_nscore[i]);
        if (bits >= lo && bits <= hi) {
            unsigned p = atomicAdd((unsigned*)s_cnt, 1u);
            if (p < KEYCAP)
                keys[p] = ((unsigned long long)bits << 32) | (0xFFFFFFFFu - (unsigned)i);
        }
    }
    __syncthreads();
    int S = min((int)*s_cnt, KEYCAP);

    if (S <= T) {
        unsigned long long mykey = (tid < S) ? keys[tid] : 0ull;
        int rank = 0;
        if (tid < S) {
            for (int j = 0; j < S; j++) rank += (keys[j] > mykey) ? 1 : 0;
        }
        __syncthreads();
        if (tid < S) keys[rank] = mykey;
        __syncthreads();
    } else {
        int nsort = 1024;
        while (nsort < S) nsort <<= 1;
        for (int i = tid; i < nsort; i += T) if (i >= S) keys[i] = 0ull;
        __syncthreads();
        for (int k = 2; k <= nsort; k <<= 1) {
            for (int j = k >> 1; j > 0; j >>= 1) {
                for (int i = tid; i < nsort; i += T) {
                    int ixj = i ^ j;
                    if (ixj > i) {
                        unsigned long long a = keys[i], b = keys[ixj];
                        bool up = ((i & k) == 0);
                        if (up ? (a < b) : (a > b)) { keys[i] = b; keys[ixj] = a; }
                    }
                }
                __syncthreads();
            }
        }
    }
    return S;
}

// general (slow-path) chunk processor — only for candidates beyond the first 512.
// caller pre-fills cbox/carea/cidx.
__device__ int nms_chunk(int cn, int kept,
                         float4* cbox, float* carea, unsigned* sprev, unsigned* cidx,
                         unsigned* mat, float4* kbox, float* karea, volatile int* s_kept)
{
    const int tid = threadIdx.x;
    const int lane = tid & 31;

    if (kept == 0) {
        for (int c = tid; c < cn; c += T) sprev[c] = 0;
    } else {
        for (int c = tid; c < cn; c += T) {
            float4 b = cbox[c]; float ba = carea[c];
            unsigned f = 0;
            for (int q = 0; q < kept; q++)
                if (iou_sup(kbox[q], karea[q], b, ba)) { f = 1; break; }
            sprev[c] = f;
        }
    }

    for (int iw = tid; iw < CH * 16; iw += T) {
        int i = iw & (CH - 1);
        int w = iw >> 9;
        int j0 = w << 5;
        if (i < cn && j0 < i) {
            float4 bi = cbox[i]; float ai = carea[i];
            int jmax = min(i, j0 + 32);
            unsigned word = 0;
            for (int j = j0; j < jmax; j++)
                if (iou_sup(cbox[j], carea[j], bi, ai)) word |= 1u << (j - j0);
            mat[w * MAT_STRIDE + i] = word;
        } else if (i < cn) {
            mat[w * MAT_STRIDE + i] = 0u;
        }
    }
    __syncthreads();

    if (tid < 32) {
        unsigned km = 0;
        int kp = kept;
        unsigned row = (lane < 16 && cn > 0) ? mat[lane * MAT_STRIDE] : 0u;
        for (int i = 0; i < cn && kp < PAD; i++) {
            unsigned nrow = (lane < 16 && i + 1 < cn) ? mat[lane * MAT_STRIDE + i + 1] : 0u;
            unsigned sp = sprev[i];
            bool clash = __any_sync(0xffffffffu, (row & km) != 0u) || (sp != 0u);
            if (!clash) {
                if (lane == 0) {
                    g_idx[kp]   = (int)cidx[i];
                    g_valid[kp] = 1.0f;
                    g_obox[kp]  = cbox[i];
                    kbox[kp]    = cbox[i];
                    karea[kp]   = carea[i];
                }
                if (lane == (i >> 5)) km |= 1u << (i & 31);
                kp++;
            }
            row = nrow;
        }
        if (lane == 0) *s_kept = kp;
    }
    __syncthreads();
    return *s_kept;
}

// ---------------- output layout ----------------
#define OFF_SC  (PAD * 4)
#define OFF_MK  (OFF_SC + PAD * N_CLS)
#define PER_F4  (MASK_SZ / 4)   // 3969

// ---------------- THE mega-kernel ----------------
__global__ __launch_bounds__(T, 1) void k_mega(
    const float* __restrict__ meta,
    const float* __restrict__ deltas,
    const float* __restrict__ props,
    const float* __restrict__ scores,
    const float* __restrict__ masks,
    float* __restrict__ out)
{
    extern __shared__ char sm[];
    unsigned*           hist  = (unsigned*)(sm);
    float4*             cbox  = (float4*)(sm);
    float*              carea = (float*)(sm + 8192);
    unsigned*           sprev = (unsigned*)(sm + 10240);
    unsigned*           cidx  = (unsigned*)(sm + 12288);
    unsigned*           mat   = (unsigned*)(sm + 14336);
    unsigned*           smat  = (unsigned*)(sm + 47360);   // [16][512]
    unsigned*           scidx = (unsigned*)(sm + 80128);   // [512]
    unsigned long long* keys  = (unsigned long long*)(sm + OFF_KEYS);
    unsigned*           s1    = (unsigned*)(sm + OFF_S1);
    float4*             kbox  = (float4*)(sm + OFF_KBOX);
    float*              karea = (float*)(sm + OFF_KAREA);
    volatile unsigned*  s_cnt   = (volatile unsigned*)(sm + OFF_SCAL);
    volatile int*       s_kept  = (volatile int*)(sm + OFF_SCAL + 4);
    volatile unsigned*  s_b     = (volatile unsigned*)(sm + OFF_SCAL + 8);
    volatile unsigned*  s_above = (volatile unsigned*)(sm + OFF_SCAL + 12);
    volatile int*       s_all   = (volatile int*)(sm + OFF_SCAL + 16);

    const int tid  = threadIdx.x;
    const int lane = tid & 31;
    const int bid  = blockIdx.x;
    const int gtid = bid * T + tid;

    // ========= phase 0: score scan only (all blocks, warp per anchor) =========
    {
        int gw = bid * 32 + (tid >> 5);
        for (int a = gw; a < N_ANCH; a += NW) {
            const float* srow = scores + (size_t)a * N_CLS;
            float bv = -INFINITY; int bc = 0;
            float ms = -INFINITY;
            for (int c = lane; c < N_CLS; c += 32) {
                float v = srow[c];
                if (v > bv) { bv = v; bc = c; }
                if (c >= 1) ms = fmaxf(ms, v);
            }
            #pragma unroll
            for (int off = 16; off; off >>= 1) {
                float ov  = __shfl_down_sync(0xffffffffu, bv, off);
                int   oc  = __shfl_down_sync(0xffffffffu, bc, off);
                float oms = __shfl_down_sync(0xffffffffu, ms, off);
                if (ov > bv || (ov == bv && oc < bc)) { bv = ov; bc = oc; }
                ms = fmaxf(ms, oms);
            }
            if (lane == 0) {
                g_nscore[a] = ms;
                g_cls[a]    = bc;
            }
        }
        for (int i = gtid; i < 16 * 512; i += GRID * T) g_mat[i] = 0u;
    }
    signal(&c_dec);

    // ========= phase 1: select + candidate box decode (block 0 only) =========
    if (bid == 0) {
        spin_ge(&c_dec, GRID);
        unsigned lo = radix_threshold(hist, s1, 0xFFFFFFFFu, TARGET, s_b, s_above, s_all);
        int S = collect_sort(keys, lo, 0xFFFFFFFFu, s_cnt);
        for (int i = tid; i < S; i += T) g_skeys[i] = keys[i];
        int cn = min(S, CH);
        for (int c = tid; c < cn; c += T) {
            int aidx = (int)(0xFFFFFFFFu - (unsigned)keys[c]);
            float4 b = decode_box(aidx, meta, deltas, props);
            g_cbox[c]  = b;
            g_carea[c] = (b.z - b.x + 1.0f) * (b.w - b.y + 1.0f);
        }
        __syncthreads();
        if (tid == 0) { g_S = S; g_lo = lo; __threadfence(); atomicExch(&f_sel, 1); }
        __syncthreads();
    }

    // ========= phase 2: bitmatrix, flat pairs over blocks 1..GRID-1 =========
    spin_ge(&f_sel, 1);
    if (bid != 0) {
        int cn = min(g_S, CH);
        for (int p = (bid - 1) * T + tid; p < NPAIR; p += (GRID - 1) * T) {
            // p -> (i, j), j < i   (float sqrt + integer fixup; 8p+1 < 2^24 exact)
            float q = sqrtf((float)(8 * p + 1));
            int i = (int)((1.0f + q) * 0.5f);
            while (i * (i - 1) / 2 > p) i--;
            while ((i + 1) * i / 2 <= p) i++;
            int j = p - i * (i - 1) / 2;
            if (i >= cn) continue;

            float4 bi = g_cbox[i];
            float4 bj = g_cbox[j];
            float  ai = g_carea[i];
            float  aj = g_carea[j];
            if (iou_sup(bj, aj, bi, ai))
                atomicOr(&g_mat[(j >> 5) * 512 + i], 1u << (j & 31));
        }
    }
    signal(&c_mat);

    // ========= phase 3: resolve (block 0 only) =========
    if (bid == 0) {
        spin_ge(&c_mat, GRID);

        int S = g_S;
        int cn0 = min(S, CH);

        for (int i = tid; i < 2048; i += T) ((uint4*)smat)[i] = ((const uint4*)g_mat)[i];
        for (int i = tid; i < cn0; i += T) scidx[i] = 0xFFFFFFFFu - (unsigned)g_skeys[i];
        if (tid == 0) *s_kept = 0;
        __syncthreads();

        // sparse group-wise resolve by warp 0
        if (tid < 32) {
            unsigned km[16];
            #pragma unroll
            for (int g = 0; g < 16; g++) km[g] = 0u;
            int kp = 0;

            #pragma unroll
            for (int g = 0; g < 16; g++) {
                if (kp >= PAD) break;
                int i = g * 32 + lane;
                bool active = i < cn0;
                unsigned r = active ? smat[g * 512 + i] : 0u;
                unsigned clash = 0;
                #pragma unroll
                for (int w = 0; w < 16; w++) {
                    if (w >= g) break;
                    clash |= (active ? smat[w * 512 + i] : 0u) & km[w];
                }
                unsigned myidx = active ? scidx[i] : 0u;

                unsigned activeM  = __ballot_sync(0xffffffffu, active);
                unsigned suspects = __ballot_sync(0xffffffffu, active && ((r != 0u) || (clash != 0u)));

                unsigned kmg;
                if (suspects == 0u) {
                    kmg = activeM;
                } else {
                    kmg = activeM & ~suspects;
                    unsigned rem = suspects;
                    while (rem) {
                        int t = __ffs(rem) - 1; rem &= rem - 1;
                        unsigned rt = __shfl_sync(0xffffffffu, r, t);
                        unsigned ct = __shfl_sync(0xffffffffu, clash, t);
                        if (ct == 0u && (rt & kmg) == 0u) kmg |= 1u << t;
                    }
                }

                int allowed = PAD - kp;
                int cnt = __popc(kmg);
                int rank = __popc(kmg & ((1u << lane) - 1u));
                bool mykeep = ((kmg >> lane) & 1u) && (rank < allowed);
                if (mykeep) {
                    g_idx[kp + rank]   = (int)myidx;
                    g_valid[kp + rank] = 1.0f;
                    g_obox[kp + rank]  = g_cbox[i];
                }
                km[g] = __ballot_sync(0xffffffffu, mykeep);
                kp += min(cnt, allowed);
            }
            if (lane == 0) *s_kept = kp;
        }
        __syncthreads();
        int kept = *s_kept;

        // general fallback (rare): more chunks / further radix rounds
        if (kept < PAD && (S > CH || g_lo > 0)) {
            for (int q = tid; q < kept; q += T) {
                float4 b = g_obox[q];
                kbox[q] = b;
                karea[q] = (b.z - b.x + 1.0f) * (b.w - b.y + 1.0f);
            }
            __syncthreads();

            for (int base = CH; base < S && kept < PAD; base += CH) {
                int cn = min(CH, S - base);
                for (int c = tid; c < cn; c += T) {
                    int aidx = (int)(0xFFFFFFFFu - (unsigned)g_skeys[base + c]);
                    cidx[c] = (unsigned)aidx;
                    float4 b = decode_box(aidx, meta, deltas, props);
                    cbox[c] = b;
                    carea[c] = (b.z - b.x + 1.0f) * (b.w - b.y + 1.0f);
                }
                __syncthreads();
                kept = nms_chunk(cn, kept, cbox, carea, sprev, cidx, mat,
                                 kbox, karea, s_kept);
            }

            if (kept < PAD && g_lo > 0) {
                unsigned hi = g_lo - 1u;
                while (kept < PAD) {
                    unsigned lo = radix_threshold(hist, s1, hi, TARGET, s_b, s_above, s_all);
                    int Sb = collect_sort(keys, lo, hi, s_cnt);
                    for (int base = 0; base < Sb && kept < PAD; base += CH) {
                        int cn = min(CH, Sb - base);
                        for (int c = tid; c < cn; c += T) {
                            int aidx = (int)(0xFFFFFFFFu - (unsigned)keys[base + c]);
                            cidx[c] = (unsigned)aidx;
                            float4 b = decode_box(aidx, meta, deltas, props);
                            cbox[c] = b;
                            carea[c] = (b.z - b.x + 1.0f) * (b.w - b.y + 1.0f);
                        }
                        __syncthreads();
                        kept = nms_chunk(cn, kept, cbox, carea, sprev, cidx, mat,
                                         kbox, karea, s_kept);
                    }
                    if (lo == 0u) break;
                    hi = lo - 1u;
                    __syncthreads();
                }
            }
        }

        for (int r = kept + tid; r < PAD; r += T) { g_idx[r] = 0; g_valid[r] = 0.0f; }
        __syncthreads();
        if (tid == 0) { __threadfence(); atomicExch(&f_res, 1); }
        __syncthreads();
    }

    // ========= phase 4: gather (all blocks) =========
    spin_ge(&f_res, 1);
    {
        for (int d = bid; d < PAD; d += GRID) {
            int idx = g_idx[d];
            float s = g_valid[d];
            const float4* src = (const float4*)(masks + (size_t)idx * MASK_SZ);
            float4* dst = (float4*)(out + OFF_MK) + (size_t)d * PER_F4;
            for (int m = tid; m < PER_F4; m += T) {
                float4 v = src[m];
                v.x *= s; v.y *= s; v.z *= s; v.w *= s;
                dst[m] = v;
            }
        }
        if (gtid < OFF_MK) {
            int e = gtid;
            if (e < OFF_SC) {
                int k = e >> 2, c = e & 3;
                const float* bp = (const float*)&g_obox[k];
                out[e] = bp[c] * g_valid[k];
            } else {
                int r = e - OFF_SC;
                int k = r / N_CLS, c = r - k * N_CLS;
                out[e] = scores[(size_t)g_idx[k] * N_CLS + c] * g_valid[k];
            }
        }
    }
    signal(&c_fin);

    // ========= phase 5: reset counters for next graph replay =========
    if (bid == 0) {
        if (tid == 0) {
            while (*(volatile int*)&c_fin < GRID) __nanosleep(64);
            c_dec = 0; f_sel = 0; c_mat = 0; f_res = 0; c_fin = 0;
            __threadfence();
        }
    }
}

// ---------------- launch ----------------
extern "C" void kernel_launch(void* const* d_in, const int* in_sizes, int n_in,
                              void* d_out, int out_size)
{
    const float* meta   = (const float*)d_in[0];
    const float* deltas = (const float*)d_in[1];
    const float* props  = (const float*)d_in[2];
    const float* scores = (const float*)d_in[3];
    const float* masks  = (const float*)d_in[4];
    float* out = (float*)d_out;

    static bool attr_done = false;
    if (!attr_done) {
        cudaFuncSetAttribute(k_mega, cudaFuncAttributeMaxDynamicSharedMemorySize, SMEM_TOTAL);
        attr_done = true;
    }

    k_mega<<<GRID, T, SMEM_TOTAL>>>(meta, deltas, props, scores, masks, out);
}